// round 9
// baseline (speedup 1.0000x reference)
#include <cuda_runtime.h>
#include <cuda_bf16.h>

#define SS 4096
#define CC 256
#define BB 2
#define NHH 4
#define HDD 64
#define NGROUPS 32
#define CPG 8
#define SCALE 0.0625f  // 1/sqrt(256)
#define LOG2E 1.4426950408889634f

// scratch (allocation-free rule: __device__ globals)
__device__ float g_norm[BB*CC*SS];
__device__ float g_att[BB*CC*SS];
__device__ __nv_bfloat16 g_qb[BB*CC*SS];
__device__ __nv_bfloat16 g_kb[BB*CC*SS];
__device__ __nv_bfloat16 g_vb[BB*CC*SS];

// ---------------- helpers ----------------
__device__ __forceinline__ float to_tf32(float x) {
    unsigned r;
    asm("cvt.rna.tf32.f32 %0, %1;" : "=r"(r) : "f"(x));
    return __uint_as_float(r);
}

__device__ __forceinline__ void mma_tf32(float c[4], const float a[4], float b0, float b1) {
    asm volatile(
        "mma.sync.aligned.m16n8k8.row.col.f32.tf32.tf32.f32 "
        "{%0,%1,%2,%3}, {%4,%5,%6,%7}, {%8,%9}, {%0,%1,%2,%3};"
        : "+f"(c[0]), "+f"(c[1]), "+f"(c[2]), "+f"(c[3])
        : "r"(__float_as_uint(a[0])), "r"(__float_as_uint(a[1])),
          "r"(__float_as_uint(a[2])), "r"(__float_as_uint(a[3])),
          "r"(__float_as_uint(b0)), "r"(__float_as_uint(b1)));
}

__device__ __forceinline__ void mma_bf16(float c[4], const unsigned a[4],
                                         unsigned b0, unsigned b1) {
    asm volatile(
        "mma.sync.aligned.m16n8k16.row.col.f32.bf16.bf16.f32 "
        "{%0,%1,%2,%3}, {%4,%5,%6,%7}, {%8,%9}, {%0,%1,%2,%3};"
        : "+f"(c[0]), "+f"(c[1]), "+f"(c[2]), "+f"(c[3])
        : "r"(a[0]), "r"(a[1]), "r"(a[2]), "r"(a[3]),
          "r"(b0), "r"(b1));
}

__device__ __forceinline__ unsigned prmtb(unsigned a, unsigned b, unsigned sel) {
    unsigned d;
    asm("prmt.b32 %0, %1, %2, %3;" : "=r"(d) : "r"(a), "r"(b), "r"(sel));
    return d;
}

__device__ __forceinline__ unsigned pack_bf16(float lo, float hi) {
    unsigned r;
    asm("cvt.rn.bf16x2.f32 %0, %1, %2;" : "=r"(r) : "f"(hi), "f"(lo));
    return r;
}

// ---------------- GroupNorm ----------------
__global__ void __launch_bounds__(256) gn_kernel(const float* __restrict__ x,
                                                 const float* __restrict__ w,
                                                 const float* __restrict__ b) {
    int grp = blockIdx.x;                       // b*32 + g
    const float* xp = x + (size_t)grp * CPG * SS;
    float* op = g_norm + (size_t)grp * CPG * SS;
    int t = threadIdx.x;
    const int n4 = CPG * SS / 4;                // 8192 float4s
    const float4* x4 = (const float4*)xp;
    float s0 = 0.f, s1 = 0.f;
    for (int i = t; i < n4; i += 256) {
        float4 v = x4[i];
        s0 += v.x + v.y + v.z + v.w;
        s1 += v.x*v.x + v.y*v.y + v.z*v.z + v.w*v.w;
    }
    __shared__ float r0[256], r1[256];
    r0[t] = s0; r1[t] = s1; __syncthreads();
    for (int o = 128; o > 0; o >>= 1) {
        if (t < o) { r0[t] += r0[t+o]; r1[t] += r1[t+o]; }
        __syncthreads();
    }
    __shared__ float mu_s, rs_s;
    if (t == 0) {
        float inv_n = 1.0f / (CPG * SS);
        float mu = r0[0] * inv_n;
        float var = r1[0] * inv_n - mu * mu;
        mu_s = mu;
        rs_s = rsqrtf(var + 1e-5f);
    }
    __syncthreads();
    float mu = mu_s, rs = rs_s;
    int g = grp % NGROUPS;
    float4* o4 = (float4*)op;
    for (int i = t; i < n4; i += 256) {
        int c = g * CPG + (i * 4) / SS;
        float wc = w[c], bc = b[c];
        float4 v = x4[i];
        v.x = (v.x - mu) * rs * wc + bc;
        v.y = (v.y - mu) * rs * wc + bc;
        v.z = (v.z - mu) * rs * wc + bc;
        v.w = (v.w - mu) * rs * wc + bc;
        o4[i] = v;
    }
}

// ---------------- tf32 MMA GEMM: C[256][4096] = A[256][256] * X[256][4096] --------
// CTA tile 128x128, 8 warps (2m x 4n), warp tile 64x32, BK=16, double buffered.
#define GST 136   // smem row stride (mod 32 == 8 -> conflict-free fragment LDS)

struct MMLoad {
    float4 a0, a1, x0, x1;
};

__device__ __forceinline__ void mm_ldg(MMLoad& L, const float* __restrict__ A,
                                       const float* __restrict__ X,
                                       int m0, int n0, int kb, int t) {
    int m = t >> 1, kk = (t & 1) * 8;
    const float* ap = &A[(size_t)(m0 + m) * CC + kb * 16 + kk];
    L.a0 = *(const float4*)ap;
    L.a1 = *(const float4*)(ap + 4);
    int k = t >> 5, n = (t & 31) * 4;
    L.x0 = *(const float4*)&X[(size_t)(kb * 16 + k) * SS + n0 + n];
    L.x1 = *(const float4*)&X[(size_t)(kb * 16 + k + 8) * SS + n0 + n];
}

__device__ __forceinline__ void mm_sts(const MMLoad& L, float* a_s, float* x_s, int t) {
    int m = t >> 1, kk = (t & 1) * 8;
    a_s[(kk + 0) * GST + m] = to_tf32(L.a0.x);
    a_s[(kk + 1) * GST + m] = to_tf32(L.a0.y);
    a_s[(kk + 2) * GST + m] = to_tf32(L.a0.z);
    a_s[(kk + 3) * GST + m] = to_tf32(L.a0.w);
    a_s[(kk + 4) * GST + m] = to_tf32(L.a1.x);
    a_s[(kk + 5) * GST + m] = to_tf32(L.a1.y);
    a_s[(kk + 6) * GST + m] = to_tf32(L.a1.z);
    a_s[(kk + 7) * GST + m] = to_tf32(L.a1.w);
    int k = t >> 5, n = (t & 31) * 4;
    float4 v0 = make_float4(to_tf32(L.x0.x), to_tf32(L.x0.y), to_tf32(L.x0.z), to_tf32(L.x0.w));
    float4 v1 = make_float4(to_tf32(L.x1.x), to_tf32(L.x1.y), to_tf32(L.x1.z), to_tf32(L.x1.w));
    *(float4*)&x_s[k * GST + n] = v0;
    *(float4*)&x_s[(k + 8) * GST + n] = v1;
}

__device__ __forceinline__ void mm_compute(const float* a_s, const float* x_s,
                                           float acc[4][4][4], int wm, int wn,
                                           int qr, int qc) {
    #pragma unroll
    for (int k8 = 0; k8 < 2; k8++) {
        float a[4][4];
        #pragma unroll
        for (int mt = 0; mt < 4; mt++) {
            int mb = wm * 64 + mt * 16;
            a[mt][0] = a_s[(k8 * 8 + qc) * GST + mb + qr];
            a[mt][1] = a_s[(k8 * 8 + qc) * GST + mb + qr + 8];
            a[mt][2] = a_s[(k8 * 8 + qc + 4) * GST + mb + qr];
            a[mt][3] = a_s[(k8 * 8 + qc + 4) * GST + mb + qr + 8];
        }
        #pragma unroll
        for (int nt = 0; nt < 4; nt++) {
            int nb = wn * 32 + nt * 8;
            float b0 = x_s[(k8 * 8 + qc) * GST + nb + qr];
            float b1 = x_s[(k8 * 8 + qc + 4) * GST + nb + qr];
            #pragma unroll
            for (int mt = 0; mt < 4; mt++)
                mma_tf32(acc[mt][nt], a[mt], b0, b1);
        }
    }
}

__device__ __forceinline__ void mm_main(const float* __restrict__ A,
                                        const float* __restrict__ X,
                                        float acc[4][4][4],
                                        float* a_sm, float* x_sm,
                                        int m0, int n0, int t, int wm, int wn,
                                        int qr, int qc) {
    MMLoad L;
    mm_ldg(L, A, X, m0, n0, 0, t);
    mm_sts(L, a_sm, x_sm, t);
    __syncthreads();
    for (int kb = 0; kb < 16; kb++) {
        int cur = kb & 1;
        if (kb < 15) mm_ldg(L, A, X, m0, n0, kb + 1, t);
        mm_compute(a_sm + cur * (16 * GST), x_sm + cur * (16 * GST), acc, wm, wn, qr, qc);
        if (kb < 15) mm_sts(L, a_sm + (cur ^ 1) * (16 * GST), x_sm + (cur ^ 1) * (16 * GST), t);
        __syncthreads();
    }
}

// QKV: z = bat*3 + which; writes bf16 outputs (Q pre-scaled by log2(e)/16)
__global__ void __launch_bounds__(256) qkv_mm_kernel(const float* __restrict__ wq,
                                                     const float* __restrict__ wk,
                                                     const float* __restrict__ wv) {
    __shared__ float a_sm[2 * 16 * GST];
    __shared__ float x_sm[2 * 16 * GST];
    int z = blockIdx.z;
    int bat = z / 3, which = z % 3;
    const float* A = (which == 0) ? wq : (which == 1) ? wk : wv;
    __nv_bfloat16* out = ((which == 0) ? g_qb : (which == 1) ? g_kb : g_vb)
                         + (size_t)bat * CC * SS;
    const float* X = g_norm + (size_t)bat * CC * SS;

    int t = threadIdx.x, lane = t & 31;
    int qr = lane >> 2, qc = lane & 3;
    int wid = t >> 5, wm = wid >> 2, wn = wid & 3;
    int m0 = blockIdx.y * 128, n0 = blockIdx.x * 128;

    float acc[4][4][4] = {};
    mm_main(A, X, acc, a_sm, x_sm, m0, n0, t, wm, wn, qr, qc);

    float sc = (which == 0) ? SCALE * LOG2E : 1.0f;
    #pragma unroll
    for (int mt = 0; mt < 4; mt++) {
        int row = m0 + wm * 64 + mt * 16 + qr;
        #pragma unroll
        for (int nt = 0; nt < 4; nt++) {
            int col = n0 + wn * 32 + nt * 8 + 2 * qc;
            *(unsigned*)&out[(size_t)row * SS + col] =
                pack_bf16(acc[mt][nt][0] * sc, acc[mt][nt][1] * sc);
            *(unsigned*)&out[(size_t)(row + 8) * SS + col] =
                pack_bf16(acc[mt][nt][2] * sc, acc[mt][nt][3] * sc);
        }
    }
}

// proj: out = wo * g_att + bo + x   (full fp32 output)
__global__ void __launch_bounds__(256) proj_mm_kernel(const float* __restrict__ wo,
                                                      const float* __restrict__ bo,
                                                      const float* __restrict__ x,
                                                      float* __restrict__ out) {
    __shared__ float a_sm[2 * 16 * GST];
    __shared__ float x_sm[2 * 16 * GST];
    int bat = blockIdx.z;
    const float* X = g_att + (size_t)bat * CC * SS;
    const float* xr = x + (size_t)bat * CC * SS;
    float* op = out + (size_t)bat * CC * SS;

    int t = threadIdx.x, lane = t & 31;
    int qr = lane >> 2, qc = lane & 3;
    int wid = t >> 5, wm = wid >> 2, wn = wid & 3;
    int m0 = blockIdx.y * 128, n0 = blockIdx.x * 128;

    float acc[4][4][4] = {};
    mm_main(wo, X, acc, a_sm, x_sm, m0, n0, t, wm, wn, qr, qc);

    #pragma unroll
    for (int mt = 0; mt < 4; mt++) {
        int row = m0 + wm * 64 + mt * 16 + qr;
        float bv0 = bo[row], bv1 = bo[row + 8];
        #pragma unroll
        for (int nt = 0; nt < 4; nt++) {
            int col = n0 + wn * 32 + nt * 8 + 2 * qc;
            size_t off0 = (size_t)row * SS + col;
            size_t off1 = (size_t)(row + 8) * SS + col;
            float2 r0 = *(const float2*)&xr[off0];
            float2 r1 = *(const float2*)&xr[off1];
            *(float2*)&op[off0] = make_float2(acc[mt][nt][0] + bv0 + r0.x,
                                              acc[mt][nt][1] + bv0 + r0.y);
            *(float2*)&op[off1] = make_float2(acc[mt][nt][2] + bv1 + r1.x,
                                              acc[mt][nt][3] + bv1 + r1.y);
        }
    }
}

// ---------------- Flash attention, bf16 m16n8k16, register P ----------------
// 128 threads = 4 warps; each warp owns 32 query rows (two m16 tiles) so every
// K/V fragment load feeds 2 MMAs. Softmax in exp2 domain (log2e baked into Q).
// ks[d2][j] stride 72 (S-frag bank 8qc+qr), vs[d][j2] stride 36 (PV bank 4qr+qc).
#define KSP 72
#define VSP 36
#define FLASH_SMEM_BYTES 18432

__global__ void __launch_bounds__(128) flash_bf16_kernel() {
    extern __shared__ float sm[];
    unsigned* ks = (unsigned*)sm;
    unsigned* vs = ks + 32 * KSP;
    unsigned* qst = (unsigned*)sm;   // transient (init only)
    float* ost = sm;                 // transient (epilogue only)

    int i0 = blockIdx.x * 128;
    int head = blockIdx.y, bat = blockIdx.z;
    size_t base = ((size_t)(bat * NHH + head)) * HDD * SS;
    const __nv_bfloat16* qp = g_qb + base;
    const __nv_bfloat16* kp = g_kb + base;
    const __nv_bfloat16* vp = g_vb + base;
    float* op = g_att + base;

    int t = threadIdx.x;
    int lane = t & 31;
    int qr = lane >> 2, qc = lane & 3;
    int w32 = (t >> 5) * 32;

    // ---- stage Q tile as vertical-d bf16 pairs: qst[i][d2], stride 36 ----
    #pragma unroll
    for (int it = 0; it < 4; it++) {
        int slot = t + it * 128;
        int d2 = slot >> 4, ig = slot & 15;
        uint4 ra = *(const uint4*)(qp + (size_t)(2 * d2) * SS + i0 + ig * 8);
        uint4 rb = *(const uint4*)(qp + (size_t)(2 * d2 + 1) * SS + i0 + ig * 8);
        unsigned u[8];
        u[0] = prmtb(ra.x, rb.x, 0x5410); u[1] = prmtb(ra.x, rb.x, 0x7632);
        u[2] = prmtb(ra.y, rb.y, 0x5410); u[3] = prmtb(ra.y, rb.y, 0x7632);
        u[4] = prmtb(ra.z, rb.z, 0x5410); u[5] = prmtb(ra.z, rb.z, 0x7632);
        u[6] = prmtb(ra.w, rb.w, 0x5410); u[7] = prmtb(ra.w, rb.w, 0x7632);
        #pragma unroll
        for (int c = 0; c < 8; c++)
            qst[(ig * 8 + c) * 36 + d2] = u[c];
    }
    __syncthreads();

    // ---- hoist Q fragments: 2 m-tiles x 4 k16-groups x 4 regs ----
    unsigned qf[2][4][4];
    #pragma unroll
    for (int m = 0; m < 2; m++) {
        int rb0 = w32 + 16 * m;
        #pragma unroll
        for (int kg = 0; kg < 4; kg++) {
            qf[m][kg][0] = qst[(rb0 + qr) * 36 + kg * 8 + qc];
            qf[m][kg][1] = qst[(rb0 + qr + 8) * 36 + kg * 8 + qc];
            qf[m][kg][2] = qst[(rb0 + qr) * 36 + kg * 8 + qc + 4];
            qf[m][kg][3] = qst[(rb0 + qr + 8) * 36 + kg * 8 + qc + 4];
        }
    }
    __syncthreads();

    float mA[2] = {-1e30f, -1e30f}, mB[2] = {-1e30f, -1e30f};
    float lA[2] = {0.f, 0.f}, lB[2] = {0.f, 0.f};
    float o[2][8][4];
    #pragma unroll
    for (int m = 0; m < 2; m++)
        #pragma unroll
        for (int nt = 0; nt < 8; nt++) {
            o[m][nt][0] = 0.f; o[m][nt][1] = 0.f;
            o[m][nt][2] = 0.f; o[m][nt][3] = 0.f;
        }

    for (int jb = 0; jb < SS; jb += 64) {
        __syncthreads();
        // ---- stage K: ks[d2][j] vertical pairs ----
        #pragma unroll
        for (int it = 0; it < 2; it++) {
            int slot = t + it * 128;
            int d2 = slot >> 3, g = slot & 7;
            uint4 ra = *(const uint4*)(kp + (size_t)(2 * d2) * SS + jb + g * 8);
            uint4 rb = *(const uint4*)(kp + (size_t)(2 * d2 + 1) * SS + jb + g * 8);
            uint4 w0, w1;
            w0.x = prmtb(ra.x, rb.x, 0x5410); w0.y = prmtb(ra.x, rb.x, 0x7632);
            w0.z = prmtb(ra.y, rb.y, 0x5410); w0.w = prmtb(ra.y, rb.y, 0x7632);
            w1.x = prmtb(ra.z, rb.z, 0x5410); w1.y = prmtb(ra.z, rb.z, 0x7632);
            w1.z = prmtb(ra.w, rb.w, 0x5410); w1.w = prmtb(ra.w, rb.w, 0x7632);
            *(uint4*)&ks[d2 * KSP + g * 8] = w0;
            *(uint4*)&ks[d2 * KSP + g * 8 + 4] = w1;
        }
        // ---- stage V: natural copy vs[d][j2] ----
        #pragma unroll
        for (int it = 0; it < 4; it++) {
            int slot = t + it * 128;
            int d = slot >> 3, g = slot & 7;
            uint4 va = *(const uint4*)(vp + (size_t)d * SS + jb + g * 8);
            *(uint4*)&vs[d * VSP + g * 4] = va;
        }
        __syncthreads();

        // ---- S = Q K^T : each B-frag pair feeds both m-tiles ----
        float s[2][8][4];
        #pragma unroll
        for (int m = 0; m < 2; m++)
            #pragma unroll
            for (int nt = 0; nt < 8; nt++) {
                s[m][nt][0] = 0.f; s[m][nt][1] = 0.f;
                s[m][nt][2] = 0.f; s[m][nt][3] = 0.f;
            }
        #pragma unroll
        for (int kg = 0; kg < 4; kg++) {
            int r0 = (kg * 8 + qc) * KSP;
            int r1 = r0 + 4 * KSP;
            #pragma unroll
            for (int nt = 0; nt < 8; nt++) {
                unsigned b0 = ks[r0 + nt * 8 + qr];
                unsigned b1 = ks[r1 + nt * 8 + qr];
                mma_bf16(s[0][nt], qf[0][kg], b0, b1);
                mma_bf16(s[1][nt], qf[1][kg], b0, b1);
            }
        }

        // ---- online softmax (exp2 domain) per m-tile ----
        #pragma unroll
        for (int m = 0; m < 2; m++) {
            float mxA = s[m][0][0], mxB = s[m][0][2];
            #pragma unroll
            for (int nt = 0; nt < 8; nt++) {
                mxA = fmaxf(mxA, fmaxf(s[m][nt][0], s[m][nt][1]));
                mxB = fmaxf(mxB, fmaxf(s[m][nt][2], s[m][nt][3]));
            }
            mxA = fmaxf(mxA, __shfl_xor_sync(0xffffffffu, mxA, 1));
            mxA = fmaxf(mxA, __shfl_xor_sync(0xffffffffu, mxA, 2));
            mxB = fmaxf(mxB, __shfl_xor_sync(0xffffffffu, mxB, 1));
            mxB = fmaxf(mxB, __shfl_xor_sync(0xffffffffu, mxB, 2));
            float mAn = fmaxf(mA[m], mxA), mBn = fmaxf(mB[m], mxB);
            float cA = exp2f(mA[m] - mAn), cB = exp2f(mB[m] - mBn);
            float sA = 0.f, sB = 0.f;
            #pragma unroll
            for (int nt = 0; nt < 8; nt++) {
                s[m][nt][0] = exp2f(s[m][nt][0] - mAn); sA += s[m][nt][0];
                s[m][nt][1] = exp2f(s[m][nt][1] - mAn); sA += s[m][nt][1];
                s[m][nt][2] = exp2f(s[m][nt][2] - mBn); sB += s[m][nt][2];
                s[m][nt][3] = exp2f(s[m][nt][3] - mBn); sB += s[m][nt][3];
            }
            sA += __shfl_xor_sync(0xffffffffu, sA, 1);
            sA += __shfl_xor_sync(0xffffffffu, sA, 2);
            sB += __shfl_xor_sync(0xffffffffu, sB, 1);
            sB += __shfl_xor_sync(0xffffffffu, sB, 2);
            lA[m] = lA[m] * cA + sA; lB[m] = lB[m] * cB + sB;
            mA[m] = mAn; mB[m] = mBn;
            #pragma unroll
            for (int nt = 0; nt < 8; nt++) {
                o[m][nt][0] *= cA; o[m][nt][1] *= cA;
                o[m][nt][2] *= cB; o[m][nt][3] *= cB;
            }
        }

        // ---- O += P V : each V-frag pair feeds both m-tiles ----
        #pragma unroll
        for (int kj = 0; kj < 4; kj++) {
            unsigned pa0[4], pa1[4];
            pa0[0] = pack_bf16(s[0][2 * kj][0],     s[0][2 * kj][1]);
            pa0[1] = pack_bf16(s[0][2 * kj][2],     s[0][2 * kj][3]);
            pa0[2] = pack_bf16(s[0][2 * kj + 1][0], s[0][2 * kj + 1][1]);
            pa0[3] = pack_bf16(s[0][2 * kj + 1][2], s[0][2 * kj + 1][3]);
            pa1[0] = pack_bf16(s[1][2 * kj][0],     s[1][2 * kj][1]);
            pa1[1] = pack_bf16(s[1][2 * kj][2],     s[1][2 * kj][3]);
            pa1[2] = pack_bf16(s[1][2 * kj + 1][0], s[1][2 * kj + 1][1]);
            pa1[3] = pack_bf16(s[1][2 * kj + 1][2], s[1][2 * kj + 1][3]);
            #pragma unroll
            for (int nt = 0; nt < 8; nt++) {
                int vr = (nt * 8 + qr) * VSP + kj * 8;
                unsigned b0 = vs[vr + qc];
                unsigned b1 = vs[vr + qc + 4];
                mma_bf16(o[0][nt], pa0, b0, b1);
                mma_bf16(o[1][nt], pa1, b0, b1);
            }
        }
    }

    // ---- normalize, stage O as [d][i] in 2 halves (stride 132), store ----
    float rA[2], rB[2];
    #pragma unroll
    for (int m = 0; m < 2; m++) { rA[m] = 1.f / lA[m]; rB[m] = 1.f / lB[m]; }
    #pragma unroll
    for (int h = 0; h < 2; h++) {
        __syncthreads();
        #pragma unroll
        for (int m = 0; m < 2; m++) {
            int rb0 = w32 + 16 * m;
            #pragma unroll
            for (int ntl = 0; ntl < 4; ntl++) {
                int nt = 4 * h + ntl;
                int rl = ntl * 8;
                ost[(rl + 2 * qc) * 132 + rb0 + qr]         = o[m][nt][0] * rA[m];
                ost[(rl + 2 * qc + 1) * 132 + rb0 + qr]     = o[m][nt][1] * rA[m];
                ost[(rl + 2 * qc) * 132 + rb0 + qr + 8]     = o[m][nt][2] * rB[m];
                ost[(rl + 2 * qc + 1) * 132 + rb0 + qr + 8] = o[m][nt][3] * rB[m];
            }
        }
        __syncthreads();
        #pragma unroll
        for (int it = 0; it < 8; it++) {
            int idx = t + it * 128;
            int dl = idx >> 5, i8 = idx & 31;
            *(float4*)&op[(size_t)(dl + 32 * h) * SS + i0 + i8 * 4] =
                *(float4*)&ost[dl * 132 + i8 * 4];
        }
    }
}

// ---------------- launch ----------------
extern "C" void kernel_launch(void* const* d_in, const int* in_sizes, int n_in,
                              void* d_out, int out_size) {
    const float* x    = (const float*)d_in[0];
    const float* gn_w = (const float*)d_in[1];
    const float* gn_b = (const float*)d_in[2];
    const float* wq   = (const float*)d_in[3];
    const float* wk   = (const float*)d_in[4];
    const float* wv   = (const float*)d_in[5];
    const float* wo   = (const float*)d_in[6];
    const float* bo   = (const float*)d_in[7];
    float* out = (float*)d_out;

    // 1) GroupNorm
    gn_kernel<<<BB * NGROUPS, 256>>>(x, gn_w, gn_b);
    // 2) Q/K/V projections (tf32 tensor core, bf16 out; Q scaled by log2e/16)
    {
        dim3 grid(SS / 128, CC / 128, BB * 3);
        qkv_mm_kernel<<<grid, 256>>>(wq, wk, wv);
    }
    // 3) flash attention (bf16 tensor core, 4 warps x 32 rows, register P)
    {
        dim3 grid(SS / 128, NHH, BB);
        flash_bf16_kernel<<<grid, 128, FLASH_SMEM_BYTES>>>();
    }
    // 4) output projection + bias + residual (tf32 tensor core)
    {
        dim3 grid(SS / 128, CC / 128, BB);
        proj_mm_kernel<<<grid, 256>>>(wo, bo, x, out);
    }
}

// round 10
// speedup vs baseline: 1.0198x; 1.0198x over previous
#include <cuda_runtime.h>
#include <cuda_bf16.h>

#define SS 4096
#define CC 256
#define BB 2
#define NHH 4
#define HDD 64
#define NGROUPS 32
#define CPG 8
#define SCALE 0.0625f  // 1/sqrt(256)
#define LOG2E 1.4426950408889634f

// scratch (allocation-free rule: __device__ globals)
__device__ float g_norm[BB*CC*SS];
__device__ float g_att[BB*CC*SS];
__device__ __nv_bfloat16 g_qb[BB*CC*SS];
__device__ __nv_bfloat16 g_kb[BB*CC*SS];
__device__ __nv_bfloat16 g_vb[BB*CC*SS];

// ---------------- helpers ----------------
__device__ __forceinline__ float to_tf32(float x) {
    unsigned r;
    asm("cvt.rna.tf32.f32 %0, %1;" : "=r"(r) : "f"(x));
    return __uint_as_float(r);
}

__device__ __forceinline__ void mma_tf32(float c[4], const float a[4], float b0, float b1) {
    asm volatile(
        "mma.sync.aligned.m16n8k8.row.col.f32.tf32.tf32.f32 "
        "{%0,%1,%2,%3}, {%4,%5,%6,%7}, {%8,%9}, {%0,%1,%2,%3};"
        : "+f"(c[0]), "+f"(c[1]), "+f"(c[2]), "+f"(c[3])
        : "r"(__float_as_uint(a[0])), "r"(__float_as_uint(a[1])),
          "r"(__float_as_uint(a[2])), "r"(__float_as_uint(a[3])),
          "r"(__float_as_uint(b0)), "r"(__float_as_uint(b1)));
}

__device__ __forceinline__ void mma_bf16(float c[4], const unsigned a[4],
                                         unsigned b0, unsigned b1) {
    asm volatile(
        "mma.sync.aligned.m16n8k16.row.col.f32.bf16.bf16.f32 "
        "{%0,%1,%2,%3}, {%4,%5,%6,%7}, {%8,%9}, {%0,%1,%2,%3};"
        : "+f"(c[0]), "+f"(c[1]), "+f"(c[2]), "+f"(c[3])
        : "r"(a[0]), "r"(a[1]), "r"(a[2]), "r"(a[3]),
          "r"(b0), "r"(b1));
}

__device__ __forceinline__ unsigned prmtb(unsigned a, unsigned b, unsigned sel) {
    unsigned d;
    asm("prmt.b32 %0, %1, %2, %3;" : "=r"(d) : "r"(a), "r"(b), "r"(sel));
    return d;
}

__device__ __forceinline__ unsigned pack_bf16(float lo, float hi) {
    unsigned r;
    asm("cvt.rn.bf16x2.f32 %0, %1, %2;" : "=r"(r) : "f"(hi), "f"(lo));
    return r;
}

// ---------------- GroupNorm ----------------
__global__ void __launch_bounds__(256) gn_kernel(const float* __restrict__ x,
                                                 const float* __restrict__ w,
                                                 const float* __restrict__ b) {
    int grp = blockIdx.x;                       // b*32 + g
    const float* xp = x + (size_t)grp * CPG * SS;
    float* op = g_norm + (size_t)grp * CPG * SS;
    int t = threadIdx.x;
    const int n4 = CPG * SS / 4;                // 8192 float4s
    const float4* x4 = (const float4*)xp;
    float s0 = 0.f, s1 = 0.f;
    for (int i = t; i < n4; i += 256) {
        float4 v = x4[i];
        s0 += v.x + v.y + v.z + v.w;
        s1 += v.x*v.x + v.y*v.y + v.z*v.z + v.w*v.w;
    }
    __shared__ float r0[256], r1[256];
    r0[t] = s0; r1[t] = s1; __syncthreads();
    for (int o = 128; o > 0; o >>= 1) {
        if (t < o) { r0[t] += r0[t+o]; r1[t] += r1[t+o]; }
        __syncthreads();
    }
    __shared__ float mu_s, rs_s;
    if (t == 0) {
        float inv_n = 1.0f / (CPG * SS);
        float mu = r0[0] * inv_n;
        float var = r1[0] * inv_n - mu * mu;
        mu_s = mu;
        rs_s = rsqrtf(var + 1e-5f);
    }
    __syncthreads();
    float mu = mu_s, rs = rs_s;
    int g = grp % NGROUPS;
    float4* o4 = (float4*)op;
    for (int i = t; i < n4; i += 256) {
        int c = g * CPG + (i * 4) / SS;
        float wc = w[c], bc = b[c];
        float4 v = x4[i];
        v.x = (v.x - mu) * rs * wc + bc;
        v.y = (v.y - mu) * rs * wc + bc;
        v.z = (v.z - mu) * rs * wc + bc;
        v.w = (v.w - mu) * rs * wc + bc;
        o4[i] = v;
    }
}

// ---------------- tf32 MMA GEMM: C[256][4096] = A[256][256] * X[256][4096] --------
// CTA tile 128x128, 8 warps (2m x 4n), warp tile 64x32, BK=16, double buffered.
#define GST 136   // smem row stride (mod 32 == 8 -> conflict-free fragment LDS)

struct MMLoad {
    float4 a0, a1, x0, x1;
};

__device__ __forceinline__ void mm_ldg(MMLoad& L, const float* __restrict__ A,
                                       const float* __restrict__ X,
                                       int m0, int n0, int kb, int t) {
    int m = t >> 1, kk = (t & 1) * 8;
    const float* ap = &A[(size_t)(m0 + m) * CC + kb * 16 + kk];
    L.a0 = *(const float4*)ap;
    L.a1 = *(const float4*)(ap + 4);
    int k = t >> 5, n = (t & 31) * 4;
    L.x0 = *(const float4*)&X[(size_t)(kb * 16 + k) * SS + n0 + n];
    L.x1 = *(const float4*)&X[(size_t)(kb * 16 + k + 8) * SS + n0 + n];
}

__device__ __forceinline__ void mm_sts(const MMLoad& L, float* a_s, float* x_s, int t) {
    int m = t >> 1, kk = (t & 1) * 8;
    a_s[(kk + 0) * GST + m] = to_tf32(L.a0.x);
    a_s[(kk + 1) * GST + m] = to_tf32(L.a0.y);
    a_s[(kk + 2) * GST + m] = to_tf32(L.a0.z);
    a_s[(kk + 3) * GST + m] = to_tf32(L.a0.w);
    a_s[(kk + 4) * GST + m] = to_tf32(L.a1.x);
    a_s[(kk + 5) * GST + m] = to_tf32(L.a1.y);
    a_s[(kk + 6) * GST + m] = to_tf32(L.a1.z);
    a_s[(kk + 7) * GST + m] = to_tf32(L.a1.w);
    int k = t >> 5, n = (t & 31) * 4;
    float4 v0 = make_float4(to_tf32(L.x0.x), to_tf32(L.x0.y), to_tf32(L.x0.z), to_tf32(L.x0.w));
    float4 v1 = make_float4(to_tf32(L.x1.x), to_tf32(L.x1.y), to_tf32(L.x1.z), to_tf32(L.x1.w));
    *(float4*)&x_s[k * GST + n] = v0;
    *(float4*)&x_s[(k + 8) * GST + n] = v1;
}

__device__ __forceinline__ void mm_compute(const float* a_s, const float* x_s,
                                           float acc[4][4][4], int wm, int wn,
                                           int qr, int qc) {
    #pragma unroll
    for (int k8 = 0; k8 < 2; k8++) {
        float a[4][4];
        #pragma unroll
        for (int mt = 0; mt < 4; mt++) {
            int mb = wm * 64 + mt * 16;
            a[mt][0] = a_s[(k8 * 8 + qc) * GST + mb + qr];
            a[mt][1] = a_s[(k8 * 8 + qc) * GST + mb + qr + 8];
            a[mt][2] = a_s[(k8 * 8 + qc + 4) * GST + mb + qr];
            a[mt][3] = a_s[(k8 * 8 + qc + 4) * GST + mb + qr + 8];
        }
        #pragma unroll
        for (int nt = 0; nt < 4; nt++) {
            int nb = wn * 32 + nt * 8;
            float b0 = x_s[(k8 * 8 + qc) * GST + nb + qr];
            float b1 = x_s[(k8 * 8 + qc + 4) * GST + nb + qr];
            #pragma unroll
            for (int mt = 0; mt < 4; mt++)
                mma_tf32(acc[mt][nt], a[mt], b0, b1);
        }
    }
}

__device__ __forceinline__ void mm_main(const float* __restrict__ A,
                                        const float* __restrict__ X,
                                        float acc[4][4][4],
                                        float* a_sm, float* x_sm,
                                        int m0, int n0, int t, int wm, int wn,
                                        int qr, int qc) {
    MMLoad L;
    mm_ldg(L, A, X, m0, n0, 0, t);
    mm_sts(L, a_sm, x_sm, t);
    __syncthreads();
    for (int kb = 0; kb < 16; kb++) {
        int cur = kb & 1;
        if (kb < 15) mm_ldg(L, A, X, m0, n0, kb + 1, t);
        mm_compute(a_sm + cur * (16 * GST), x_sm + cur * (16 * GST), acc, wm, wn, qr, qc);
        if (kb < 15) mm_sts(L, a_sm + (cur ^ 1) * (16 * GST), x_sm + (cur ^ 1) * (16 * GST), t);
        __syncthreads();
    }
}

// QKV: z = bat*3 + which; writes bf16 outputs (Q pre-scaled by log2(e)/16)
__global__ void __launch_bounds__(256) qkv_mm_kernel(const float* __restrict__ wq,
                                                     const float* __restrict__ wk,
                                                     const float* __restrict__ wv) {
    __shared__ float a_sm[2 * 16 * GST];
    __shared__ float x_sm[2 * 16 * GST];
    int z = blockIdx.z;
    int bat = z / 3, which = z % 3;
    const float* A = (which == 0) ? wq : (which == 1) ? wk : wv;
    __nv_bfloat16* out = ((which == 0) ? g_qb : (which == 1) ? g_kb : g_vb)
                         + (size_t)bat * CC * SS;
    const float* X = g_norm + (size_t)bat * CC * SS;

    int t = threadIdx.x, lane = t & 31;
    int qr = lane >> 2, qc = lane & 3;
    int wid = t >> 5, wm = wid >> 2, wn = wid & 3;
    int m0 = blockIdx.y * 128, n0 = blockIdx.x * 128;

    float acc[4][4][4] = {};
    mm_main(A, X, acc, a_sm, x_sm, m0, n0, t, wm, wn, qr, qc);

    float sc = (which == 0) ? SCALE * LOG2E : 1.0f;
    #pragma unroll
    for (int mt = 0; mt < 4; mt++) {
        int row = m0 + wm * 64 + mt * 16 + qr;
        #pragma unroll
        for (int nt = 0; nt < 4; nt++) {
            int col = n0 + wn * 32 + nt * 8 + 2 * qc;
            *(unsigned*)&out[(size_t)row * SS + col] =
                pack_bf16(acc[mt][nt][0] * sc, acc[mt][nt][1] * sc);
            *(unsigned*)&out[(size_t)(row + 8) * SS + col] =
                pack_bf16(acc[mt][nt][2] * sc, acc[mt][nt][3] * sc);
        }
    }
}

// proj: out = wo * g_att + bo + x   (full fp32 output)
__global__ void __launch_bounds__(256) proj_mm_kernel(const float* __restrict__ wo,
                                                      const float* __restrict__ bo,
                                                      const float* __restrict__ x,
                                                      float* __restrict__ out) {
    __shared__ float a_sm[2 * 16 * GST];
    __shared__ float x_sm[2 * 16 * GST];
    int bat = blockIdx.z;
    const float* X = g_att + (size_t)bat * CC * SS;
    const float* xr = x + (size_t)bat * CC * SS;
    float* op = out + (size_t)bat * CC * SS;

    int t = threadIdx.x, lane = t & 31;
    int qr = lane >> 2, qc = lane & 3;
    int wid = t >> 5, wm = wid >> 2, wn = wid & 3;
    int m0 = blockIdx.y * 128, n0 = blockIdx.x * 128;

    float acc[4][4][4] = {};
    mm_main(wo, X, acc, a_sm, x_sm, m0, n0, t, wm, wn, qr, qc);

    #pragma unroll
    for (int mt = 0; mt < 4; mt++) {
        int row = m0 + wm * 64 + mt * 16 + qr;
        float bv0 = bo[row], bv1 = bo[row + 8];
        #pragma unroll
        for (int nt = 0; nt < 4; nt++) {
            int col = n0 + wn * 32 + nt * 8 + 2 * qc;
            size_t off0 = (size_t)row * SS + col;
            size_t off1 = (size_t)(row + 8) * SS + col;
            float2 r0 = *(const float2*)&xr[off0];
            float2 r1 = *(const float2*)&xr[off1];
            *(float2*)&op[off0] = make_float2(acc[mt][nt][0] + bv0 + r0.x,
                                              acc[mt][nt][1] + bv0 + r0.y);
            *(float2*)&op[off1] = make_float2(acc[mt][nt][2] + bv1 + r1.x,
                                              acc[mt][nt][3] + bv1 + r1.y);
        }
    }
}

// ---------------- Flash attention, bf16 m16n8k16, register P ----------------
// 128 threads = 4 warps; each warp owns 32 query rows (two m16 tiles) so every
// K/V fragment load feeds 2 MMAs. Softmax in exp2 domain (log2e baked into Q).
// ks[d2][j] stride 72 (S-frag bank 8qc+qr), vs[d][j2] stride 36 (PV bank 4qr+qc).
#define KSP 72
#define VSP 36
#define FLASH_SMEM_BYTES 18432

__global__ void __launch_bounds__(128) flash_bf16_kernel() {
    extern __shared__ float sm[];
    unsigned* ks = (unsigned*)sm;
    unsigned* vs = ks + 32 * KSP;
    unsigned* qst = (unsigned*)sm;   // transient (init only)
    float* ost = sm;                 // transient (epilogue only)

    int i0 = blockIdx.x * 128;
    int head = blockIdx.y, bat = blockIdx.z;
    size_t base = ((size_t)(bat * NHH + head)) * HDD * SS;
    const __nv_bfloat16* qp = g_qb + base;
    const __nv_bfloat16* kp = g_kb + base;
    const __nv_bfloat16* vp = g_vb + base;
    float* op = g_att + base;

    int t = threadIdx.x;
    int lane = t & 31;
    int qr = lane >> 2, qc = lane & 3;
    int w32 = (t >> 5) * 32;

    // ---- stage Q tile as vertical-d bf16 pairs: qst[i][d2], stride 36 ----
    #pragma unroll
    for (int it = 0; it < 4; it++) {
        int slot = t + it * 128;
        int d2 = slot >> 4, ig = slot & 15;
        uint4 ra = *(const uint4*)(qp + (size_t)(2 * d2) * SS + i0 + ig * 8);
        uint4 rb = *(const uint4*)(qp + (size_t)(2 * d2 + 1) * SS + i0 + ig * 8);
        unsigned u[8];
        u[0] = prmtb(ra.x, rb.x, 0x5410); u[1] = prmtb(ra.x, rb.x, 0x7632);
        u[2] = prmtb(ra.y, rb.y, 0x5410); u[3] = prmtb(ra.y, rb.y, 0x7632);
        u[4] = prmtb(ra.z, rb.z, 0x5410); u[5] = prmtb(ra.z, rb.z, 0x7632);
        u[6] = prmtb(ra.w, rb.w, 0x5410); u[7] = prmtb(ra.w, rb.w, 0x7632);
        #pragma unroll
        for (int c = 0; c < 8; c++)
            qst[(ig * 8 + c) * 36 + d2] = u[c];
    }
    __syncthreads();

    // ---- hoist Q fragments: 2 m-tiles x 4 k16-groups x 4 regs ----
    unsigned qf[2][4][4];
    #pragma unroll
    for (int m = 0; m < 2; m++) {
        int rb0 = w32 + 16 * m;
        #pragma unroll
        for (int kg = 0; kg < 4; kg++) {
            qf[m][kg][0] = qst[(rb0 + qr) * 36 + kg * 8 + qc];
            qf[m][kg][1] = qst[(rb0 + qr + 8) * 36 + kg * 8 + qc];
            qf[m][kg][2] = qst[(rb0 + qr) * 36 + kg * 8 + qc + 4];
            qf[m][kg][3] = qst[(rb0 + qr + 8) * 36 + kg * 8 + qc + 4];
        }
    }
    __syncthreads();

    float mA[2] = {-1e30f, -1e30f}, mB[2] = {-1e30f, -1e30f};
    float lA[2] = {0.f, 0.f}, lB[2] = {0.f, 0.f};
    float o[2][8][4];
    #pragma unroll
    for (int m = 0; m < 2; m++)
        #pragma unroll
        for (int nt = 0; nt < 8; nt++) {
            o[m][nt][0] = 0.f; o[m][nt][1] = 0.f;
            o[m][nt][2] = 0.f; o[m][nt][3] = 0.f;
        }

    for (int jb = 0; jb < SS; jb += 64) {
        __syncthreads();
        // ---- stage K: ks[d2][j] vertical pairs ----
        #pragma unroll
        for (int it = 0; it < 2; it++) {
            int slot = t + it * 128;
            int d2 = slot >> 3, g = slot & 7;
            uint4 ra = *(const uint4*)(kp + (size_t)(2 * d2) * SS + jb + g * 8);
            uint4 rb = *(const uint4*)(kp + (size_t)(2 * d2 + 1) * SS + jb + g * 8);
            uint4 w0, w1;
            w0.x = prmtb(ra.x, rb.x, 0x5410); w0.y = prmtb(ra.x, rb.x, 0x7632);
            w0.z = prmtb(ra.y, rb.y, 0x5410); w0.w = prmtb(ra.y, rb.y, 0x7632);
            w1.x = prmtb(ra.z, rb.z, 0x5410); w1.y = prmtb(ra.z, rb.z, 0x7632);
            w1.z = prmtb(ra.w, rb.w, 0x5410); w1.w = prmtb(ra.w, rb.w, 0x7632);
            *(uint4*)&ks[d2 * KSP + g * 8] = w0;
            *(uint4*)&ks[d2 * KSP + g * 8 + 4] = w1;
        }
        // ---- stage V: natural copy vs[d][j2] ----
        #pragma unroll
        for (int it = 0; it < 4; it++) {
            int slot = t + it * 128;
            int d = slot >> 3, g = slot & 7;
            uint4 va = *(const uint4*)(vp + (size_t)d * SS + jb + g * 8);
            *(uint4*)&vs[d * VSP + g * 4] = va;
        }
        __syncthreads();

        // ---- S = Q K^T : each B-frag pair feeds both m-tiles ----
        float s[2][8][4];
        #pragma unroll
        for (int m = 0; m < 2; m++)
            #pragma unroll
            for (int nt = 0; nt < 8; nt++) {
                s[m][nt][0] = 0.f; s[m][nt][1] = 0.f;
                s[m][nt][2] = 0.f; s[m][nt][3] = 0.f;
            }
        #pragma unroll
        for (int kg = 0; kg < 4; kg++) {
            int r0 = (kg * 8 + qc) * KSP;
            int r1 = r0 + 4 * KSP;
            #pragma unroll
            for (int nt = 0; nt < 8; nt++) {
                unsigned b0 = ks[r0 + nt * 8 + qr];
                unsigned b1 = ks[r1 + nt * 8 + qr];
                mma_bf16(s[0][nt], qf[0][kg], b0, b1);
                mma_bf16(s[1][nt], qf[1][kg], b0, b1);
            }
        }

        // ---- online softmax (exp2 domain) per m-tile ----
        #pragma unroll
        for (int m = 0; m < 2; m++) {
            float mxA = s[m][0][0], mxB = s[m][0][2];
            #pragma unroll
            for (int nt = 0; nt < 8; nt++) {
                mxA = fmaxf(mxA, fmaxf(s[m][nt][0], s[m][nt][1]));
                mxB = fmaxf(mxB, fmaxf(s[m][nt][2], s[m][nt][3]));
            }
            mxA = fmaxf(mxA, __shfl_xor_sync(0xffffffffu, mxA, 1));
            mxA = fmaxf(mxA, __shfl_xor_sync(0xffffffffu, mxA, 2));
            mxB = fmaxf(mxB, __shfl_xor_sync(0xffffffffu, mxB, 1));
            mxB = fmaxf(mxB, __shfl_xor_sync(0xffffffffu, mxB, 2));
            float mAn = fmaxf(mA[m], mxA), mBn = fmaxf(mB[m], mxB);
            float cA = exp2f(mA[m] - mAn), cB = exp2f(mB[m] - mBn);
            float sA = 0.f, sB = 0.f;
            #pragma unroll
            for (int nt = 0; nt < 8; nt++) {
                s[m][nt][0] = exp2f(s[m][nt][0] - mAn); sA += s[m][nt][0];
                s[m][nt][1] = exp2f(s[m][nt][1] - mAn); sA += s[m][nt][1];
                s[m][nt][2] = exp2f(s[m][nt][2] - mBn); sB += s[m][nt][2];
                s[m][nt][3] = exp2f(s[m][nt][3] - mBn); sB += s[m][nt][3];
            }
            sA += __shfl_xor_sync(0xffffffffu, sA, 1);
            sA += __shfl_xor_sync(0xffffffffu, sA, 2);
            sB += __shfl_xor_sync(0xffffffffu, sB, 1);
            sB += __shfl_xor_sync(0xffffffffu, sB, 2);
            lA[m] = lA[m] * cA + sA; lB[m] = lB[m] * cB + sB;
            mA[m] = mAn; mB[m] = mBn;
            #pragma unroll
            for (int nt = 0; nt < 8; nt++) {
                o[m][nt][0] *= cA; o[m][nt][1] *= cA;
                o[m][nt][2] *= cB; o[m][nt][3] *= cB;
            }
        }

        // ---- O += P V : each V-frag pair feeds both m-tiles ----
        #pragma unroll
        for (int kj = 0; kj < 4; kj++) {
            unsigned pa0[4], pa1[4];
            pa0[0] = pack_bf16(s[0][2 * kj][0],     s[0][2 * kj][1]);
            pa0[1] = pack_bf16(s[0][2 * kj][2],     s[0][2 * kj][3]);
            pa0[2] = pack_bf16(s[0][2 * kj + 1][0], s[0][2 * kj + 1][1]);
            pa0[3] = pack_bf16(s[0][2 * kj + 1][2], s[0][2 * kj + 1][3]);
            pa1[0] = pack_bf16(s[1][2 * kj][0],     s[1][2 * kj][1]);
            pa1[1] = pack_bf16(s[1][2 * kj][2],     s[1][2 * kj][3]);
            pa1[2] = pack_bf16(s[1][2 * kj + 1][0], s[1][2 * kj + 1][1]);
            pa1[3] = pack_bf16(s[1][2 * kj + 1][2], s[1][2 * kj + 1][3]);
            #pragma unroll
            for (int nt = 0; nt < 8; nt++) {
                int vr = (nt * 8 + qr) * VSP + kj * 8;
                unsigned b0 = vs[vr + qc];
                unsigned b1 = vs[vr + qc + 4];
                mma_bf16(o[0][nt], pa0, b0, b1);
                mma_bf16(o[1][nt], pa1, b0, b1);
            }
        }
    }

    // ---- normalize, stage O as [d][i] in 2 halves (stride 132), store ----
    float rA[2], rB[2];
    #pragma unroll
    for (int m = 0; m < 2; m++) { rA[m] = 1.f / lA[m]; rB[m] = 1.f / lB[m]; }
    #pragma unroll
    for (int h = 0; h < 2; h++) {
        __syncthreads();
        #pragma unroll
        for (int m = 0; m < 2; m++) {
            int rb0 = w32 + 16 * m;
            #pragma unroll
            for (int ntl = 0; ntl < 4; ntl++) {
                int nt = 4 * h + ntl;
                int rl = ntl * 8;
                ost[(rl + 2 * qc) * 132 + rb0 + qr]         = o[m][nt][0] * rA[m];
                ost[(rl + 2 * qc + 1) * 132 + rb0 + qr]     = o[m][nt][1] * rA[m];
                ost[(rl + 2 * qc) * 132 + rb0 + qr + 8]     = o[m][nt][2] * rB[m];
                ost[(rl + 2 * qc + 1) * 132 + rb0 + qr + 8] = o[m][nt][3] * rB[m];
            }
        }
        __syncthreads();
        #pragma unroll
        for (int it = 0; it < 8; it++) {
            int idx = t + it * 128;
            int dl = idx >> 5, i8 = idx & 31;
            *(float4*)&op[(size_t)(dl + 32 * h) * SS + i0 + i8 * 4] =
                *(float4*)&ost[dl * 132 + i8 * 4];
        }
    }
}

// ---------------- launch ----------------
extern "C" void kernel_launch(void* const* d_in, const int* in_sizes, int n_in,
                              void* d_out, int out_size) {
    const float* x    = (const float*)d_in[0];
    const float* gn_w = (const float*)d_in[1];
    const float* gn_b = (const float*)d_in[2];
    const float* wq   = (const float*)d_in[3];
    const float* wk   = (const float*)d_in[4];
    const float* wv   = (const float*)d_in[5];
    const float* wo   = (const float*)d_in[6];
    const float* bo   = (const float*)d_in[7];
    float* out = (float*)d_out;

    // 1) GroupNorm
    gn_kernel<<<BB * NGROUPS, 256>>>(x, gn_w, gn_b);
    // 2) Q/K/V projections (tf32 tensor core, bf16 out; Q scaled by log2e/16)
    {
        dim3 grid(SS / 128, CC / 128, BB * 3);
        qkv_mm_kernel<<<grid, 256>>>(wq, wk, wv);
    }
    // 3) flash attention (bf16 tensor core, 4 warps x 32 rows, register P)
    {
        dim3 grid(SS / 128, NHH, BB);
        flash_bf16_kernel<<<grid, 128, FLASH_SMEM_BYTES>>>();
    }
    // 4) output projection + bias + residual (tf32 tensor core)
    {
        dim3 grid(SS / 128, CC / 128, BB);
        proj_mm_kernel<<<grid, 256>>>(wo, bo, x, out);
    }
}

// round 11
// speedup vs baseline: 1.0618x; 1.0412x over previous
#include <cuda_runtime.h>
#include <cuda_bf16.h>

#define SS 4096
#define CC 256
#define BB 2
#define NHH 4
#define HDD 64
#define NGROUPS 32
#define CPG 8
#define SCALE 0.0625f  // 1/sqrt(256)
#define LOG2E 1.4426950408889634f

// scratch (allocation-free rule: __device__ globals)
__device__ float g_norm[BB*CC*SS];
__device__ float g_att[BB*CC*SS];
__device__ __nv_bfloat16 g_qb[BB*CC*SS];
__device__ __nv_bfloat16 g_kb[BB*CC*SS];
__device__ __nv_bfloat16 g_vb[BB*CC*SS];

// ---------------- helpers ----------------
__device__ __forceinline__ float to_tf32(float x) {
    unsigned r;
    asm("cvt.rna.tf32.f32 %0, %1;" : "=r"(r) : "f"(x));
    return __uint_as_float(r);
}

__device__ __forceinline__ void mma_tf32(float c[4], const float a[4], float b0, float b1) {
    asm volatile(
        "mma.sync.aligned.m16n8k8.row.col.f32.tf32.tf32.f32 "
        "{%0,%1,%2,%3}, {%4,%5,%6,%7}, {%8,%9}, {%0,%1,%2,%3};"
        : "+f"(c[0]), "+f"(c[1]), "+f"(c[2]), "+f"(c[3])
        : "r"(__float_as_uint(a[0])), "r"(__float_as_uint(a[1])),
          "r"(__float_as_uint(a[2])), "r"(__float_as_uint(a[3])),
          "r"(__float_as_uint(b0)), "r"(__float_as_uint(b1)));
}

__device__ __forceinline__ void mma_bf16(float c[4], const unsigned a[4],
                                         unsigned b0, unsigned b1) {
    asm volatile(
        "mma.sync.aligned.m16n8k16.row.col.f32.bf16.bf16.f32 "
        "{%0,%1,%2,%3}, {%4,%5,%6,%7}, {%8,%9}, {%0,%1,%2,%3};"
        : "+f"(c[0]), "+f"(c[1]), "+f"(c[2]), "+f"(c[3])
        : "r"(a[0]), "r"(a[1]), "r"(a[2]), "r"(a[3]),
          "r"(b0), "r"(b1));
}

__device__ __forceinline__ unsigned prmtb(unsigned a, unsigned b, unsigned sel) {
    unsigned d;
    asm("prmt.b32 %0, %1, %2, %3;" : "=r"(d) : "r"(a), "r"(b), "r"(sel));
    return d;
}

__device__ __forceinline__ unsigned pack_bf16(float lo, float hi) {
    unsigned r;
    asm("cvt.rn.bf16x2.f32 %0, %1, %2;" : "=r"(r) : "f"(hi), "f"(lo));
    return r;
}

// ---------------- GroupNorm ----------------
__global__ void __launch_bounds__(256) gn_kernel(const float* __restrict__ x,
                                                 const float* __restrict__ w,
                                                 const float* __restrict__ b) {
    int grp = blockIdx.x;                       // b*32 + g
    const float* xp = x + (size_t)grp * CPG * SS;
    float* op = g_norm + (size_t)grp * CPG * SS;
    int t = threadIdx.x;
    const int n4 = CPG * SS / 4;                // 8192 float4s
    const float4* x4 = (const float4*)xp;
    float s0 = 0.f, s1 = 0.f;
    for (int i = t; i < n4; i += 256) {
        float4 v = x4[i];
        s0 += v.x + v.y + v.z + v.w;
        s1 += v.x*v.x + v.y*v.y + v.z*v.z + v.w*v.w;
    }
    __shared__ float r0[256], r1[256];
    r0[t] = s0; r1[t] = s1; __syncthreads();
    for (int o = 128; o > 0; o >>= 1) {
        if (t < o) { r0[t] += r0[t+o]; r1[t] += r1[t+o]; }
        __syncthreads();
    }
    __shared__ float mu_s, rs_s;
    if (t == 0) {
        float inv_n = 1.0f / (CPG * SS);
        float mu = r0[0] * inv_n;
        float var = r1[0] * inv_n - mu * mu;
        mu_s = mu;
        rs_s = rsqrtf(var + 1e-5f);
    }
    __syncthreads();
    float mu = mu_s, rs = rs_s;
    int g = grp % NGROUPS;
    float4* o4 = (float4*)op;
    for (int i = t; i < n4; i += 256) {
        int c = g * CPG + (i * 4) / SS;
        float wc = w[c], bc = b[c];
        float4 v = x4[i];
        v.x = (v.x - mu) * rs * wc + bc;
        v.y = (v.y - mu) * rs * wc + bc;
        v.z = (v.z - mu) * rs * wc + bc;
        v.w = (v.w - mu) * rs * wc + bc;
        o4[i] = v;
    }
}

// ---------------- tf32 MMA GEMM: C[256][4096] = A[256][256] * X[256][4096] --------
// CTA tile 128M x 64N (2x grid -> >=2 CTAs/SM), 8 warps (4m x 2n), warp 32x32,
// BK=16, double buffered.
#define GST 136   // a_sm row stride (mod 32 == 8 -> conflict-free fragment LDS)
#define XST 72    // x_sm row stride (mod 32 == 8)

struct MMLoad {
    float4 a0, a1, x0;
};

__device__ __forceinline__ void mm_ldg(MMLoad& L, const float* __restrict__ A,
                                       const float* __restrict__ X,
                                       int m0, int n0, int kb, int t) {
    int m = t >> 1, kk = (t & 1) * 8;
    const float* ap = &A[(size_t)(m0 + m) * CC + kb * 16 + kk];
    L.a0 = *(const float4*)ap;
    L.a1 = *(const float4*)(ap + 4);
    int k = t >> 4, n = (t & 15) * 4;
    L.x0 = *(const float4*)&X[(size_t)(kb * 16 + k) * SS + n0 + n];
}

__device__ __forceinline__ void mm_sts(const MMLoad& L, float* a_s, float* x_s, int t) {
    int m = t >> 1, kk = (t & 1) * 8;
    a_s[(kk + 0) * GST + m] = to_tf32(L.a0.x);
    a_s[(kk + 1) * GST + m] = to_tf32(L.a0.y);
    a_s[(kk + 2) * GST + m] = to_tf32(L.a0.z);
    a_s[(kk + 3) * GST + m] = to_tf32(L.a0.w);
    a_s[(kk + 4) * GST + m] = to_tf32(L.a1.x);
    a_s[(kk + 5) * GST + m] = to_tf32(L.a1.y);
    a_s[(kk + 6) * GST + m] = to_tf32(L.a1.z);
    a_s[(kk + 7) * GST + m] = to_tf32(L.a1.w);
    int k = t >> 4, n = (t & 15) * 4;
    float4 v0 = make_float4(to_tf32(L.x0.x), to_tf32(L.x0.y), to_tf32(L.x0.z), to_tf32(L.x0.w));
    *(float4*)&x_s[k * XST + n] = v0;
}

__device__ __forceinline__ void mm_compute(const float* a_s, const float* x_s,
                                           float acc[2][4][4], int wm, int wn,
                                           int qr, int qc) {
    #pragma unroll
    for (int k8 = 0; k8 < 2; k8++) {
        float a[2][4];
        #pragma unroll
        for (int mt = 0; mt < 2; mt++) {
            int mb = wm * 32 + mt * 16;
            a[mt][0] = a_s[(k8 * 8 + qc) * GST + mb + qr];
            a[mt][1] = a_s[(k8 * 8 + qc) * GST + mb + qr + 8];
            a[mt][2] = a_s[(k8 * 8 + qc + 4) * GST + mb + qr];
            a[mt][3] = a_s[(k8 * 8 + qc + 4) * GST + mb + qr + 8];
        }
        #pragma unroll
        for (int nt = 0; nt < 4; nt++) {
            int nb = wn * 32 + nt * 8;
            float b0 = x_s[(k8 * 8 + qc) * XST + nb + qr];
            float b1 = x_s[(k8 * 8 + qc + 4) * XST + nb + qr];
            #pragma unroll
            for (int mt = 0; mt < 2; mt++)
                mma_tf32(acc[mt][nt], a[mt], b0, b1);
        }
    }
}

__device__ __forceinline__ void mm_main(const float* __restrict__ A,
                                        const float* __restrict__ X,
                                        float acc[2][4][4],
                                        float* a_sm, float* x_sm,
                                        int m0, int n0, int t, int wm, int wn,
                                        int qr, int qc) {
    MMLoad L;
    mm_ldg(L, A, X, m0, n0, 0, t);
    mm_sts(L, a_sm, x_sm, t);
    __syncthreads();
    for (int kb = 0; kb < 16; kb++) {
        int cur = kb & 1;
        if (kb < 15) mm_ldg(L, A, X, m0, n0, kb + 1, t);
        mm_compute(a_sm + cur * (16 * GST), x_sm + cur * (16 * XST), acc, wm, wn, qr, qc);
        if (kb < 15) mm_sts(L, a_sm + (cur ^ 1) * (16 * GST), x_sm + (cur ^ 1) * (16 * XST), t);
        __syncthreads();
    }
}

// QKV: z = bat*3 + which; writes bf16 outputs (Q pre-scaled by log2(e)/16)
__global__ void __launch_bounds__(256) qkv_mm_kernel(const float* __restrict__ wq,
                                                     const float* __restrict__ wk,
                                                     const float* __restrict__ wv) {
    __shared__ float a_sm[2 * 16 * GST];
    __shared__ float x_sm[2 * 16 * XST];
    int z = blockIdx.z;
    int bat = z / 3, which = z % 3;
    const float* A = (which == 0) ? wq : (which == 1) ? wk : wv;
    __nv_bfloat16* out = ((which == 0) ? g_qb : (which == 1) ? g_kb : g_vb)
                         + (size_t)bat * CC * SS;
    const float* X = g_norm + (size_t)bat * CC * SS;

    int t = threadIdx.x, lane = t & 31;
    int qr = lane >> 2, qc = lane & 3;
    int wid = t >> 5, wm = wid >> 1, wn = wid & 1;
    int m0 = blockIdx.y * 128, n0 = blockIdx.x * 64;

    float acc[2][4][4] = {};
    mm_main(A, X, acc, a_sm, x_sm, m0, n0, t, wm, wn, qr, qc);

    float sc = (which == 0) ? SCALE * LOG2E : 1.0f;
    #pragma unroll
    for (int mt = 0; mt < 2; mt++) {
        int row = m0 + wm * 32 + mt * 16 + qr;
        #pragma unroll
        for (int nt = 0; nt < 4; nt++) {
            int col = n0 + wn * 32 + nt * 8 + 2 * qc;
            *(unsigned*)&out[(size_t)row * SS + col] =
                pack_bf16(acc[mt][nt][0] * sc, acc[mt][nt][1] * sc);
            *(unsigned*)&out[(size_t)(row + 8) * SS + col] =
                pack_bf16(acc[mt][nt][2] * sc, acc[mt][nt][3] * sc);
        }
    }
}

// proj: out = wo * g_att + bo + x   (full fp32 output)
__global__ void __launch_bounds__(256) proj_mm_kernel(const float* __restrict__ wo,
                                                      const float* __restrict__ bo,
                                                      const float* __restrict__ x,
                                                      float* __restrict__ out) {
    __shared__ float a_sm[2 * 16 * GST];
    __shared__ float x_sm[2 * 16 * XST];
    int bat = blockIdx.z;
    const float* X = g_att + (size_t)bat * CC * SS;
    const float* xr = x + (size_t)bat * CC * SS;
    float* op = out + (size_t)bat * CC * SS;

    int t = threadIdx.x, lane = t & 31;
    int qr = lane >> 2, qc = lane & 3;
    int wid = t >> 5, wm = wid >> 1, wn = wid & 1;
    int m0 = blockIdx.y * 128, n0 = blockIdx.x * 64;

    float acc[2][4][4] = {};
    mm_main(wo, X, acc, a_sm, x_sm, m0, n0, t, wm, wn, qr, qc);

    #pragma unroll
    for (int mt = 0; mt < 2; mt++) {
        int row = m0 + wm * 32 + mt * 16 + qr;
        float bv0 = bo[row], bv1 = bo[row + 8];
        #pragma unroll
        for (int nt = 0; nt < 4; nt++) {
            int col = n0 + wn * 32 + nt * 8 + 2 * qc;
            size_t off0 = (size_t)row * SS + col;
            size_t off1 = (size_t)(row + 8) * SS + col;
            float2 r0 = *(const float2*)&xr[off0];
            float2 r1 = *(const float2*)&xr[off1];
            *(float2*)&op[off0] = make_float2(acc[mt][nt][0] + bv0 + r0.x,
                                              acc[mt][nt][1] + bv0 + r0.y);
            *(float2*)&op[off1] = make_float2(acc[mt][nt][2] + bv1 + r1.x,
                                              acc[mt][nt][3] + bv1 + r1.y);
        }
    }
}

// ---------------- Flash attention, bf16 m16n8k16, register P ----------------
// 128 threads = 4 warps; each warp owns 32 query rows (two m16 tiles).
// K/V smem DOUBLE-BUFFERED with LDG prefetch one full iteration ahead;
// single __syncthreads per iteration.
// ks[d2][j] stride 72 (S-frag bank 8qc+qr), vs[d][j2] stride 36 (PV bank 4qr+qc).
#define KSP 72
#define VSP 36
#define KVBUF (32 * KSP + 64 * VSP)          // 4608 uints per buffer
#define FLASH_SMEM_BYTES (2 * KVBUF * 4)     // 36864 B

struct KVregs {
    uint4 ka[2], kb[2];   // raw K rows (PRMT deferred to STS)
    uint4 v[4];
};

__device__ __forceinline__ void kv_ldg(KVregs& L,
                                       const __nv_bfloat16* __restrict__ kp,
                                       const __nv_bfloat16* __restrict__ vp,
                                       int jb, int t) {
    #pragma unroll
    for (int it = 0; it < 2; it++) {
        int slot = t + it * 128;
        int d2 = slot >> 3, g = slot & 7;
        L.ka[it] = *(const uint4*)(kp + (size_t)(2 * d2) * SS + jb + g * 8);
        L.kb[it] = *(const uint4*)(kp + (size_t)(2 * d2 + 1) * SS + jb + g * 8);
    }
    #pragma unroll
    for (int it = 0; it < 4; it++) {
        int slot = t + it * 128;
        int d = slot >> 3, g = slot & 7;
        L.v[it] = *(const uint4*)(vp + (size_t)d * SS + jb + g * 8);
    }
}

__device__ __forceinline__ void kv_sts(const KVregs& L, unsigned* ks, unsigned* vs, int t) {
    #pragma unroll
    for (int it = 0; it < 2; it++) {
        int slot = t + it * 128;
        int d2 = slot >> 3, g = slot & 7;
        uint4 ra = L.ka[it], rb = L.kb[it];
        uint4 w0, w1;
        w0.x = prmtb(ra.x, rb.x, 0x5410); w0.y = prmtb(ra.x, rb.x, 0x7632);
        w0.z = prmtb(ra.y, rb.y, 0x5410); w0.w = prmtb(ra.y, rb.y, 0x7632);
        w1.x = prmtb(ra.z, rb.z, 0x5410); w1.y = prmtb(ra.z, rb.z, 0x7632);
        w1.z = prmtb(ra.w, rb.w, 0x5410); w1.w = prmtb(ra.w, rb.w, 0x7632);
        *(uint4*)&ks[d2 * KSP + g * 8] = w0;
        *(uint4*)&ks[d2 * KSP + g * 8 + 4] = w1;
    }
    #pragma unroll
    for (int it = 0; it < 4; it++) {
        int slot = t + it * 128;
        int d = slot >> 3, g = slot & 7;
        *(uint4*)&vs[d * VSP + g * 4] = L.v[it];
    }
}

__global__ void __launch_bounds__(128) flash_bf16_kernel() {
    extern __shared__ float sm[];
    unsigned* sbuf = (unsigned*)sm;
    unsigned* qst = (unsigned*)sm;   // transient (init only)
    float* ost = sm;                 // transient (epilogue only)

    int i0 = blockIdx.x * 128;
    int head = blockIdx.y, bat = blockIdx.z;
    size_t base = ((size_t)(bat * NHH + head)) * HDD * SS;
    const __nv_bfloat16* qp = g_qb + base;
    const __nv_bfloat16* kp = g_kb + base;
    const __nv_bfloat16* vp = g_vb + base;
    float* op = g_att + base;

    int t = threadIdx.x;
    int lane = t & 31;
    int qr = lane >> 2, qc = lane & 3;
    int w32 = (t >> 5) * 32;

    // ---- stage Q tile as vertical-d bf16 pairs: qst[i][d2], stride 36 ----
    #pragma unroll
    for (int it = 0; it < 4; it++) {
        int slot = t + it * 128;
        int d2 = slot >> 4, ig = slot & 15;
        uint4 ra = *(const uint4*)(qp + (size_t)(2 * d2) * SS + i0 + ig * 8);
        uint4 rb = *(const uint4*)(qp + (size_t)(2 * d2 + 1) * SS + i0 + ig * 8);
        unsigned u[8];
        u[0] = prmtb(ra.x, rb.x, 0x5410); u[1] = prmtb(ra.x, rb.x, 0x7632);
        u[2] = prmtb(ra.y, rb.y, 0x5410); u[3] = prmtb(ra.y, rb.y, 0x7632);
        u[4] = prmtb(ra.z, rb.z, 0x5410); u[5] = prmtb(ra.z, rb.z, 0x7632);
        u[6] = prmtb(ra.w, rb.w, 0x5410); u[7] = prmtb(ra.w, rb.w, 0x7632);
        #pragma unroll
        for (int c = 0; c < 8; c++)
            qst[(ig * 8 + c) * 36 + d2] = u[c];
    }
    __syncthreads();

    // ---- hoist Q fragments: 2 m-tiles x 4 k16-groups x 4 regs ----
    unsigned qf[2][4][4];
    #pragma unroll
    for (int m = 0; m < 2; m++) {
        int rb0 = w32 + 16 * m;
        #pragma unroll
        for (int kg = 0; kg < 4; kg++) {
            qf[m][kg][0] = qst[(rb0 + qr) * 36 + kg * 8 + qc];
            qf[m][kg][1] = qst[(rb0 + qr + 8) * 36 + kg * 8 + qc];
            qf[m][kg][2] = qst[(rb0 + qr) * 36 + kg * 8 + qc + 4];
            qf[m][kg][3] = qst[(rb0 + qr + 8) * 36 + kg * 8 + qc + 4];
        }
    }
    __syncthreads();

    float mA[2] = {-1e30f, -1e30f}, mB[2] = {-1e30f, -1e30f};
    float lA[2] = {0.f, 0.f}, lB[2] = {0.f, 0.f};
    float o[2][8][4];
    #pragma unroll
    for (int m = 0; m < 2; m++)
        #pragma unroll
        for (int nt = 0; nt < 8; nt++) {
            o[m][nt][0] = 0.f; o[m][nt][1] = 0.f;
            o[m][nt][2] = 0.f; o[m][nt][3] = 0.f;
        }

    // ---- prologue: stage tile 0 into buf0, prefetch tile 1 into regs ----
    KVregs L;
    kv_ldg(L, kp, vp, 0, t);
    kv_sts(L, sbuf, sbuf + 32 * KSP, t);
    kv_ldg(L, kp, vp, 64, t);
    __syncthreads();

    int cur = 0;
    for (int i = 0; i < 64; i++) {
        unsigned* ks = sbuf + cur * KVBUF;
        unsigned* vs = ks + 32 * KSP;

        // ---- S = Q K^T : each B-frag pair feeds both m-tiles ----
        float s[2][8][4];
        #pragma unroll
        for (int m = 0; m < 2; m++)
            #pragma unroll
            for (int nt = 0; nt < 8; nt++) {
                s[m][nt][0] = 0.f; s[m][nt][1] = 0.f;
                s[m][nt][2] = 0.f; s[m][nt][3] = 0.f;
            }
        #pragma unroll
        for (int kg = 0; kg < 4; kg++) {
            int r0 = (kg * 8 + qc) * KSP;
            int r1 = r0 + 4 * KSP;
            #pragma unroll
            for (int nt = 0; nt < 8; nt++) {
                unsigned b0 = ks[r0 + nt * 8 + qr];
                unsigned b1 = ks[r1 + nt * 8 + qr];
                mma_bf16(s[0][nt], qf[0][kg], b0, b1);
                mma_bf16(s[1][nt], qf[1][kg], b0, b1);
            }
        }

        // ---- online softmax (exp2 domain) per m-tile ----
        #pragma unroll
        for (int m = 0; m < 2; m++) {
            float mxA = s[m][0][0], mxB = s[m][0][2];
            #pragma unroll
            for (int nt = 0; nt < 8; nt++) {
                mxA = fmaxf(mxA, fmaxf(s[m][nt][0], s[m][nt][1]));
                mxB = fmaxf(mxB, fmaxf(s[m][nt][2], s[m][nt][3]));
            }
            mxA = fmaxf(mxA, __shfl_xor_sync(0xffffffffu, mxA, 1));
            mxA = fmaxf(mxA, __shfl_xor_sync(0xffffffffu, mxA, 2));
            mxB = fmaxf(mxB, __shfl_xor_sync(0xffffffffu, mxB, 1));
            mxB = fmaxf(mxB, __shfl_xor_sync(0xffffffffu, mxB, 2));
            float mAn = fmaxf(mA[m], mxA), mBn = fmaxf(mB[m], mxB);
            float cA = exp2f(mA[m] - mAn), cB = exp2f(mB[m] - mBn);
            float sA = 0.f, sB = 0.f;
            #pragma unroll
            for (int nt = 0; nt < 8; nt++) {
                s[m][nt][0] = exp2f(s[m][nt][0] - mAn); sA += s[m][nt][0];
                s[m][nt][1] = exp2f(s[m][nt][1] - mAn); sA += s[m][nt][1];
                s[m][nt][2] = exp2f(s[m][nt][2] - mBn); sB += s[m][nt][2];
                s[m][nt][3] = exp2f(s[m][nt][3] - mBn); sB += s[m][nt][3];
            }
            sA += __shfl_xor_sync(0xffffffffu, sA, 1);
            sA += __shfl_xor_sync(0xffffffffu, sA, 2);
            sB += __shfl_xor_sync(0xffffffffu, sB, 1);
            sB += __shfl_xor_sync(0xffffffffu, sB, 2);
            lA[m] = lA[m] * cA + sA; lB[m] = lB[m] * cB + sB;
            mA[m] = mAn; mB[m] = mBn;
            #pragma unroll
            for (int nt = 0; nt < 8; nt++) {
                o[m][nt][0] *= cA; o[m][nt][1] *= cA;
                o[m][nt][2] *= cB; o[m][nt][3] *= cB;
            }
        }

        // ---- O += P V : each V-frag pair feeds both m-tiles ----
        #pragma unroll
        for (int kj = 0; kj < 4; kj++) {
            unsigned pa0[4], pa1[4];
            pa0[0] = pack_bf16(s[0][2 * kj][0],     s[0][2 * kj][1]);
            pa0[1] = pack_bf16(s[0][2 * kj][2],     s[0][2 * kj][3]);
            pa0[2] = pack_bf16(s[0][2 * kj + 1][0], s[0][2 * kj + 1][1]);
            pa0[3] = pack_bf16(s[0][2 * kj + 1][2], s[0][2 * kj + 1][3]);
            pa1[0] = pack_bf16(s[1][2 * kj][0],     s[1][2 * kj][1]);
            pa1[1] = pack_bf16(s[1][2 * kj][2],     s[1][2 * kj][3]);
            pa1[2] = pack_bf16(s[1][2 * kj + 1][0], s[1][2 * kj + 1][1]);
            pa1[3] = pack_bf16(s[1][2 * kj + 1][2], s[1][2 * kj + 1][3]);
            #pragma unroll
            for (int nt = 0; nt < 8; nt++) {
                int vr = (nt * 8 + qr) * VSP + kj * 8;
                unsigned b0 = vs[vr + qc];
                unsigned b1 = vs[vr + qc + 4];
                mma_bf16(o[0][nt], pa0, b0, b1);
                mma_bf16(o[1][nt], pa1, b0, b1);
            }
        }

        // ---- pipeline: store prefetched tile i+1, sync, prefetch tile i+2 ----
        if (i < 63) {
            unsigned* ksn = sbuf + (cur ^ 1) * KVBUF;
            kv_sts(L, ksn, ksn + 32 * KSP, t);
        }
        __syncthreads();
        if (i < 62) kv_ldg(L, kp, vp, (i + 2) * 64, t);
        cur ^= 1;
    }

    // ---- normalize, stage O as [d][i] in 2 halves (stride 132), store ----
    float rA[2], rB[2];
    #pragma unroll
    for (int m = 0; m < 2; m++) { rA[m] = 1.f / lA[m]; rB[m] = 1.f / lB[m]; }
    #pragma unroll
    for (int h = 0; h < 2; h++) {
        if (h) __syncthreads();
        #pragma unroll
        for (int m = 0; m < 2; m++) {
            int rb0 = w32 + 16 * m;
            #pragma unroll
            for (int ntl = 0; ntl < 4; ntl++) {
                int nt = 4 * h + ntl;
                int rl = ntl * 8;
                ost[(rl + 2 * qc) * 132 + rb0 + qr]         = o[m][nt][0] * rA[m];
                ost[(rl + 2 * qc + 1) * 132 + rb0 + qr]     = o[m][nt][1] * rA[m];
                ost[(rl + 2 * qc) * 132 + rb0 + qr + 8]     = o[m][nt][2] * rB[m];
                ost[(rl + 2 * qc + 1) * 132 + rb0 + qr + 8] = o[m][nt][3] * rB[m];
            }
        }
        __syncthreads();
        #pragma unroll
        for (int it = 0; it < 8; it++) {
            int idx = t + it * 128;
            int dl = idx >> 5, i8 = idx & 31;
            *(float4*)&op[(size_t)(dl + 32 * h) * SS + i0 + i8 * 4] =
                *(float4*)&ost[dl * 132 + i8 * 4];
        }
    }
}

// ---------------- launch ----------------
extern "C" void kernel_launch(void* const* d_in, const int* in_sizes, int n_in,
                              void* d_out, int out_size) {
    const float* x    = (const float*)d_in[0];
    const float* gn_w = (const float*)d_in[1];
    const float* gn_b = (const float*)d_in[2];
    const float* wq   = (const float*)d_in[3];
    const float* wk   = (const float*)d_in[4];
    const float* wv   = (const float*)d_in[5];
    const float* wo   = (const float*)d_in[6];
    const float* bo   = (const float*)d_in[7];
    float* out = (float*)d_out;

    // 1) GroupNorm
    gn_kernel<<<BB * NGROUPS, 256>>>(x, gn_w, gn_b);
    // 2) Q/K/V projections (tf32 tensor core, bf16 out; Q scaled by log2e/16)
    {
        dim3 grid(SS / 64, CC / 128, BB * 3);
        qkv_mm_kernel<<<grid, 256>>>(wq, wk, wv);
    }
    // 3) flash attention (bf16 tensor core, double-buffered K/V pipeline)
    {
        dim3 grid(SS / 128, NHH, BB);
        flash_bf16_kernel<<<grid, 128, FLASH_SMEM_BYTES>>>();
    }
    // 4) output projection + bias + residual (tf32 tensor core)
    {
        dim3 grid(SS / 64, CC / 128, BB);
        proj_mm_kernel<<<grid, 256>>>(wo, bo, x, out);
    }
}

// round 12
// speedup vs baseline: 1.1324x; 1.0665x over previous
#include <cuda_runtime.h>
#include <cuda_bf16.h>

#define SS 4096
#define CC 256
#define BB 2
#define NHH 4
#define HDD 64
#define NGROUPS 32
#define CPG 8
#define SCALE 0.0625f  // 1/sqrt(256)
#define LOG2E 1.4426950408889634f

// scratch (allocation-free rule: __device__ globals)
__device__ float g_norm[BB*CC*SS];
__device__ float g_att[BB*CC*SS];
__device__ __nv_bfloat16 g_qb[BB*CC*SS];
__device__ __nv_bfloat16 g_kb[BB*CC*SS];
__device__ __nv_bfloat16 g_vb[BB*CC*SS];

// ---------------- helpers ----------------
__device__ __forceinline__ void mma_tf32(float c[4], const float a[4], float b0, float b1) {
    asm volatile(
        "mma.sync.aligned.m16n8k8.row.col.f32.tf32.tf32.f32 "
        "{%0,%1,%2,%3}, {%4,%5,%6,%7}, {%8,%9}, {%0,%1,%2,%3};"
        : "+f"(c[0]), "+f"(c[1]), "+f"(c[2]), "+f"(c[3])
        : "r"(__float_as_uint(a[0])), "r"(__float_as_uint(a[1])),
          "r"(__float_as_uint(a[2])), "r"(__float_as_uint(a[3])),
          "r"(__float_as_uint(b0)), "r"(__float_as_uint(b1)));
}

__device__ __forceinline__ void mma_bf16(float c[4], const unsigned a[4],
                                         unsigned b0, unsigned b1) {
    asm volatile(
        "mma.sync.aligned.m16n8k16.row.col.f32.bf16.bf16.f32 "
        "{%0,%1,%2,%3}, {%4,%5,%6,%7}, {%8,%9}, {%0,%1,%2,%3};"
        : "+f"(c[0]), "+f"(c[1]), "+f"(c[2]), "+f"(c[3])
        : "r"(a[0]), "r"(a[1]), "r"(a[2]), "r"(a[3]),
          "r"(b0), "r"(b1));
}

__device__ __forceinline__ unsigned prmtb(unsigned a, unsigned b, unsigned sel) {
    unsigned d;
    asm("prmt.b32 %0, %1, %2, %3;" : "=r"(d) : "r"(a), "r"(b), "r"(sel));
    return d;
}

__device__ __forceinline__ unsigned pack_bf16(float lo, float hi) {
    unsigned r;
    asm("cvt.rn.bf16x2.f32 %0, %1, %2;" : "=r"(r) : "f"(hi), "f"(lo));
    return r;
}

__device__ __forceinline__ void cp16(unsigned saddr, const void* g) {
    asm volatile("cp.async.cg.shared.global [%0], [%1], 16;" :: "r"(saddr), "l"(g));
}
__device__ __forceinline__ void cp_commit() {
    asm volatile("cp.async.commit_group;");
}
template <int N>
__device__ __forceinline__ void cp_wait() {
    asm volatile("cp.async.wait_group %0;" :: "n"(N));
}

// ---------------- GroupNorm ----------------
__global__ void __launch_bounds__(256) gn_kernel(const float* __restrict__ x,
                                                 const float* __restrict__ w,
                                                 const float* __restrict__ b) {
    int grp = blockIdx.x;                       // b*32 + g
    const float* xp = x + (size_t)grp * CPG * SS;
    float* op = g_norm + (size_t)grp * CPG * SS;
    int t = threadIdx.x;
    const int n4 = CPG * SS / 4;                // 8192 float4s
    const float4* x4 = (const float4*)xp;
    float s0 = 0.f, s1 = 0.f;
    for (int i = t; i < n4; i += 256) {
        float4 v = x4[i];
        s0 += v.x + v.y + v.z + v.w;
        s1 += v.x*v.x + v.y*v.y + v.z*v.z + v.w*v.w;
    }
    __shared__ float r0[256], r1[256];
    r0[t] = s0; r1[t] = s1; __syncthreads();
    for (int o = 128; o > 0; o >>= 1) {
        if (t < o) { r0[t] += r0[t+o]; r1[t] += r1[t+o]; }
        __syncthreads();
    }
    __shared__ float mu_s, rs_s;
    if (t == 0) {
        float inv_n = 1.0f / (CPG * SS);
        float mu = r0[0] * inv_n;
        float var = r1[0] * inv_n - mu * mu;
        mu_s = mu;
        rs_s = rsqrtf(var + 1e-5f);
    }
    __syncthreads();
    float mu = mu_s, rs = rs_s;
    int g = grp % NGROUPS;
    float4* o4 = (float4*)op;
    for (int i = t; i < n4; i += 256) {
        int c = g * CPG + (i * 4) / SS;
        float wc = w[c], bc = b[c];
        float4 v = x4[i];
        v.x = (v.x - mu) * rs * wc + bc;
        v.y = (v.y - mu) * rs * wc + bc;
        v.z = (v.z - mu) * rs * wc + bc;
        v.w = (v.w - mu) * rs * wc + bc;
        o4[i] = v;
    }
}

// ---------------- tf32 MMA GEMM, cp.async 3-stage pipeline ----------------
// C[256][4096] = A[256][256] * X[256][4096]; CTA tile 128M x 64N, 8 warps
// (4m x 2n), warp 32x32, BK=16. A staged natural [m][k] stride 20 (bank
// 20qr+qc all-distinct), X natural [k][n] stride 72 (8qc+qr all-distinct).
// mma.tf32 consumes raw fp32 (HW truncates mantissa).
#define AST 20
#define XST2 72
#define STAGE_F (128 * AST + 16 * XST2)   // 3712 floats per stage
#define NSTAGE 3

__device__ __forceinline__ void mm_issue(unsigned sb, const float* __restrict__ A,
                                         const float* __restrict__ X,
                                         int m0, int n0, int kb, int t) {
    // A: 512 chunks of 16B (128 rows x 4), 2 per thread
    int c0 = t * 2;
    int r0 = c0 >> 2, ch0 = c0 & 3;
    cp16(sb + (unsigned)(r0 * AST + ch0 * 4) * 4,
         &A[(size_t)(m0 + r0) * CC + kb * 16 + ch0 * 4]);
    int c1 = c0 + 1;
    int r1 = c1 >> 2, ch1 = c1 & 3;
    cp16(sb + (unsigned)(r1 * AST + ch1 * 4) * 4,
         &A[(size_t)(m0 + r1) * CC + kb * 16 + ch1 * 4]);
    // X: 256 chunks (16 rows x 16), 1 per thread
    int xr = t >> 4, xc = t & 15;
    cp16(sb + (unsigned)(128 * AST + xr * XST2 + xc * 4) * 4,
         &X[(size_t)(kb * 16 + xr) * SS + n0 + xc * 4]);
}

__device__ __forceinline__ void mm_compute(const float* a_s, const float* x_s,
                                           float acc[2][4][4], int wm, int wn,
                                           int qr, int qc) {
    #pragma unroll
    for (int k8 = 0; k8 < 2; k8++) {
        float a[2][4];
        #pragma unroll
        for (int mt = 0; mt < 2; mt++) {
            int mb = wm * 32 + mt * 16;
            a[mt][0] = a_s[(mb + qr) * AST + k8 * 8 + qc];
            a[mt][1] = a_s[(mb + qr + 8) * AST + k8 * 8 + qc];
            a[mt][2] = a_s[(mb + qr) * AST + k8 * 8 + qc + 4];
            a[mt][3] = a_s[(mb + qr + 8) * AST + k8 * 8 + qc + 4];
        }
        #pragma unroll
        for (int nt = 0; nt < 4; nt++) {
            int nb = wn * 32 + nt * 8;
            float b0 = x_s[(k8 * 8 + qc) * XST2 + nb + qr];
            float b1 = x_s[(k8 * 8 + qc + 4) * XST2 + nb + qr];
            #pragma unroll
            for (int mt = 0; mt < 2; mt++)
                mma_tf32(acc[mt][nt], a[mt], b0, b1);
        }
    }
}

__device__ __forceinline__ void mm_main(const float* __restrict__ A,
                                        const float* __restrict__ X,
                                        float acc[2][4][4], float* ps,
                                        int m0, int n0, int t, int wm, int wn,
                                        int qr, int qc) {
    unsigned sb = (unsigned)__cvta_generic_to_shared(ps);
    mm_issue(sb, A, X, m0, n0, 0, t);
    cp_commit();
    mm_issue(sb + STAGE_F * 4, A, X, m0, n0, 1, t);
    cp_commit();
    for (int kb = 0; kb < 16; kb++) {
        cp_wait<1>();
        __syncthreads();
        int st = kb % NSTAGE;
        mm_compute(ps + st * STAGE_F, ps + st * STAGE_F + 128 * AST,
                   acc, wm, wn, qr, qc);
        if (kb < 14)
            mm_issue(sb + ((kb + 2) % NSTAGE) * STAGE_F * 4, A, X, m0, n0, kb + 2, t);
        cp_commit();
    }
}

// QKV: z = bat*3 + which; writes bf16 outputs (Q pre-scaled by log2(e)/16)
__global__ void __launch_bounds__(256) qkv_mm_kernel(const float* __restrict__ wq,
                                                     const float* __restrict__ wk,
                                                     const float* __restrict__ wv) {
    __shared__ float ps[NSTAGE * STAGE_F];
    int z = blockIdx.z;
    int bat = z / 3, which = z % 3;
    const float* A = (which == 0) ? wq : (which == 1) ? wk : wv;
    __nv_bfloat16* out = ((which == 0) ? g_qb : (which == 1) ? g_kb : g_vb)
                         + (size_t)bat * CC * SS;
    const float* X = g_norm + (size_t)bat * CC * SS;

    int t = threadIdx.x, lane = t & 31;
    int qr = lane >> 2, qc = lane & 3;
    int wid = t >> 5, wm = wid >> 1, wn = wid & 1;
    int m0 = blockIdx.y * 128, n0 = blockIdx.x * 64;

    float acc[2][4][4] = {};
    mm_main(A, X, acc, ps, m0, n0, t, wm, wn, qr, qc);

    float sc = (which == 0) ? SCALE * LOG2E : 1.0f;
    #pragma unroll
    for (int mt = 0; mt < 2; mt++) {
        int row = m0 + wm * 32 + mt * 16 + qr;
        #pragma unroll
        for (int nt = 0; nt < 4; nt++) {
            int col = n0 + wn * 32 + nt * 8 + 2 * qc;
            *(unsigned*)&out[(size_t)row * SS + col] =
                pack_bf16(acc[mt][nt][0] * sc, acc[mt][nt][1] * sc);
            *(unsigned*)&out[(size_t)(row + 8) * SS + col] =
                pack_bf16(acc[mt][nt][2] * sc, acc[mt][nt][3] * sc);
        }
    }
}

// proj: out = wo * g_att + bo + x   (full fp32 output)
__global__ void __launch_bounds__(256) proj_mm_kernel(const float* __restrict__ wo,
                                                      const float* __restrict__ bo,
                                                      const float* __restrict__ x,
                                                      float* __restrict__ out) {
    __shared__ float ps[NSTAGE * STAGE_F];
    int bat = blockIdx.z;
    const float* X = g_att + (size_t)bat * CC * SS;
    const float* xr = x + (size_t)bat * CC * SS;
    float* op = out + (size_t)bat * CC * SS;

    int t = threadIdx.x, lane = t & 31;
    int qr = lane >> 2, qc = lane & 3;
    int wid = t >> 5, wm = wid >> 1, wn = wid & 1;
    int m0 = blockIdx.y * 128, n0 = blockIdx.x * 64;

    float acc[2][4][4] = {};
    mm_main(wo, X, acc, ps, m0, n0, t, wm, wn, qr, qc);

    #pragma unroll
    for (int mt = 0; mt < 2; mt++) {
        int row = m0 + wm * 32 + mt * 16 + qr;
        float bv0 = bo[row], bv1 = bo[row + 8];
        #pragma unroll
        for (int nt = 0; nt < 4; nt++) {
            int col = n0 + wn * 32 + nt * 8 + 2 * qc;
            size_t off0 = (size_t)row * SS + col;
            size_t off1 = (size_t)(row + 8) * SS + col;
            float2 r0 = *(const float2*)&xr[off0];
            float2 r1 = *(const float2*)&xr[off1];
            *(float2*)&op[off0] = make_float2(acc[mt][nt][0] + bv0 + r0.x,
                                              acc[mt][nt][1] + bv0 + r0.y);
            *(float2*)&op[off1] = make_float2(acc[mt][nt][2] + bv1 + r1.x,
                                              acc[mt][nt][3] + bv1 + r1.y);
        }
    }
}

// ---------------- Flash attention, bf16 m16n8k16, register P ----------------
// 128 threads = 4 warps; each warp owns 32 query rows (two m16 tiles).
// K/V smem double-buffered with LDG prefetch one iteration ahead.
#define KSP 72
#define VSP 36
#define KVBUF (32 * KSP + 64 * VSP)          // 4608 uints per buffer
#define FLASH_SMEM_BYTES (2 * KVBUF * 4)     // 36864 B

struct KVregs {
    uint4 ka[2], kb[2];   // raw K rows (PRMT deferred to STS)
    uint4 v[4];
};

__device__ __forceinline__ void kv_ldg(KVregs& L,
                                       const __nv_bfloat16* __restrict__ kp,
                                       const __nv_bfloat16* __restrict__ vp,
                                       int jb, int t) {
    #pragma unroll
    for (int it = 0; it < 2; it++) {
        int slot = t + it * 128;
        int d2 = slot >> 3, g = slot & 7;
        L.ka[it] = *(const uint4*)(kp + (size_t)(2 * d2) * SS + jb + g * 8);
        L.kb[it] = *(const uint4*)(kp + (size_t)(2 * d2 + 1) * SS + jb + g * 8);
    }
    #pragma unroll
    for (int it = 0; it < 4; it++) {
        int slot = t + it * 128;
        int d = slot >> 3, g = slot & 7;
        L.v[it] = *(const uint4*)(vp + (size_t)d * SS + jb + g * 8);
    }
}

__device__ __forceinline__ void kv_sts(const KVregs& L, unsigned* ks, unsigned* vs, int t) {
    #pragma unroll
    for (int it = 0; it < 2; it++) {
        int slot = t + it * 128;
        int d2 = slot >> 3, g = slot & 7;
        uint4 ra = L.ka[it], rb = L.kb[it];
        uint4 w0, w1;
        w0.x = prmtb(ra.x, rb.x, 0x5410); w0.y = prmtb(ra.x, rb.x, 0x7632);
        w0.z = prmtb(ra.y, rb.y, 0x5410); w0.w = prmtb(ra.y, rb.y, 0x7632);
        w1.x = prmtb(ra.z, rb.z, 0x5410); w1.y = prmtb(ra.z, rb.z, 0x7632);
        w1.z = prmtb(ra.w, rb.w, 0x5410); w1.w = prmtb(ra.w, rb.w, 0x7632);
        *(uint4*)&ks[d2 * KSP + g * 8] = w0;
        *(uint4*)&ks[d2 * KSP + g * 8 + 4] = w1;
    }
    #pragma unroll
    for (int it = 0; it < 4; it++) {
        int slot = t + it * 128;
        int d = slot >> 3, g = slot & 7;
        *(uint4*)&vs[d * VSP + g * 4] = L.v[it];
    }
}

__global__ void __launch_bounds__(128) flash_bf16_kernel() {
    extern __shared__ float sm[];
    unsigned* sbuf = (unsigned*)sm;
    unsigned* qst = (unsigned*)sm;   // transient (init only)
    float* ost = sm;                 // transient (epilogue only)

    int i0 = blockIdx.x * 128;
    int head = blockIdx.y, bat = blockIdx.z;
    size_t base = ((size_t)(bat * NHH + head)) * HDD * SS;
    const __nv_bfloat16* qp = g_qb + base;
    const __nv_bfloat16* kp = g_kb + base;
    const __nv_bfloat16* vp = g_vb + base;
    float* op = g_att + base;

    int t = threadIdx.x;
    int lane = t & 31;
    int qr = lane >> 2, qc = lane & 3;
    int w32 = (t >> 5) * 32;

    // ---- stage Q tile as vertical-d bf16 pairs: qst[i][d2], stride 36 ----
    #pragma unroll
    for (int it = 0; it < 4; it++) {
        int slot = t + it * 128;
        int d2 = slot >> 4, ig = slot & 15;
        uint4 ra = *(const uint4*)(qp + (size_t)(2 * d2) * SS + i0 + ig * 8);
        uint4 rb = *(const uint4*)(qp + (size_t)(2 * d2 + 1) * SS + i0 + ig * 8);
        unsigned u[8];
        u[0] = prmtb(ra.x, rb.x, 0x5410); u[1] = prmtb(ra.x, rb.x, 0x7632);
        u[2] = prmtb(ra.y, rb.y, 0x5410); u[3] = prmtb(ra.y, rb.y, 0x7632);
        u[4] = prmtb(ra.z, rb.z, 0x5410); u[5] = prmtb(ra.z, rb.z, 0x7632);
        u[6] = prmtb(ra.w, rb.w, 0x5410); u[7] = prmtb(ra.w, rb.w, 0x7632);
        #pragma unroll
        for (int c = 0; c < 8; c++)
            qst[(ig * 8 + c) * 36 + d2] = u[c];
    }
    __syncthreads();

    // ---- hoist Q fragments: 2 m-tiles x 4 k16-groups x 4 regs ----
    unsigned qf[2][4][4];
    #pragma unroll
    for (int m = 0; m < 2; m++) {
        int rb0 = w32 + 16 * m;
        #pragma unroll
        for (int kg = 0; kg < 4; kg++) {
            qf[m][kg][0] = qst[(rb0 + qr) * 36 + kg * 8 + qc];
            qf[m][kg][1] = qst[(rb0 + qr + 8) * 36 + kg * 8 + qc];
            qf[m][kg][2] = qst[(rb0 + qr) * 36 + kg * 8 + qc + 4];
            qf[m][kg][3] = qst[(rb0 + qr + 8) * 36 + kg * 8 + qc + 4];
        }
    }
    __syncthreads();

    float mA[2] = {-1e30f, -1e30f}, mB[2] = {-1e30f, -1e30f};
    float lA[2] = {0.f, 0.f}, lB[2] = {0.f, 0.f};
    float o[2][8][4];
    #pragma unroll
    for (int m = 0; m < 2; m++)
        #pragma unroll
        for (int nt = 0; nt < 8; nt++) {
            o[m][nt][0] = 0.f; o[m][nt][1] = 0.f;
            o[m][nt][2] = 0.f; o[m][nt][3] = 0.f;
        }

    // ---- prologue: stage tile 0 into buf0, prefetch tile 1 into regs ----
    KVregs L;
    kv_ldg(L, kp, vp, 0, t);
    kv_sts(L, sbuf, sbuf + 32 * KSP, t);
    kv_ldg(L, kp, vp, 64, t);
    __syncthreads();

    int cur = 0;
    for (int i = 0; i < 64; i++) {
        unsigned* ks = sbuf + cur * KVBUF;
        unsigned* vs = ks + 32 * KSP;

        // ---- S = Q K^T : each B-frag pair feeds both m-tiles ----
        float s[2][8][4];
        #pragma unroll
        for (int m = 0; m < 2; m++)
            #pragma unroll
            for (int nt = 0; nt < 8; nt++) {
                s[m][nt][0] = 0.f; s[m][nt][1] = 0.f;
                s[m][nt][2] = 0.f; s[m][nt][3] = 0.f;
            }
        #pragma unroll
        for (int kg = 0; kg < 4; kg++) {
            int r0 = (kg * 8 + qc) * KSP;
            int r1 = r0 + 4 * KSP;
            #pragma unroll
            for (int nt = 0; nt < 8; nt++) {
                unsigned b0 = ks[r0 + nt * 8 + qr];
                unsigned b1 = ks[r1 + nt * 8 + qr];
                mma_bf16(s[0][nt], qf[0][kg], b0, b1);
                mma_bf16(s[1][nt], qf[1][kg], b0, b1);
            }
        }

        // ---- online softmax (exp2 domain) per m-tile ----
        #pragma unroll
        for (int m = 0; m < 2; m++) {
            float mxA = s[m][0][0], mxB = s[m][0][2];
            #pragma unroll
            for (int nt = 0; nt < 8; nt++) {
                mxA = fmaxf(mxA, fmaxf(s[m][nt][0], s[m][nt][1]));
                mxB = fmaxf(mxB, fmaxf(s[m][nt][2], s[m][nt][3]));
            }
            mxA = fmaxf(mxA, __shfl_xor_sync(0xffffffffu, mxA, 1));
            mxA = fmaxf(mxA, __shfl_xor_sync(0xffffffffu, mxA, 2));
            mxB = fmaxf(mxB, __shfl_xor_sync(0xffffffffu, mxB, 1));
            mxB = fmaxf(mxB, __shfl_xor_sync(0xffffffffu, mxB, 2));
            float mAn = fmaxf(mA[m], mxA), mBn = fmaxf(mB[m], mxB);
            float cA = exp2f(mA[m] - mAn), cB = exp2f(mB[m] - mBn);
            float sA = 0.f, sB = 0.f;
            #pragma unroll
            for (int nt = 0; nt < 8; nt++) {
                s[m][nt][0] = exp2f(s[m][nt][0] - mAn); sA += s[m][nt][0];
                s[m][nt][1] = exp2f(s[m][nt][1] - mAn); sA += s[m][nt][1];
                s[m][nt][2] = exp2f(s[m][nt][2] - mBn); sB += s[m][nt][2];
                s[m][nt][3] = exp2f(s[m][nt][3] - mBn); sB += s[m][nt][3];
            }
            sA += __shfl_xor_sync(0xffffffffu, sA, 1);
            sA += __shfl_xor_sync(0xffffffffu, sA, 2);
            sB += __shfl_xor_sync(0xffffffffu, sB, 1);
            sB += __shfl_xor_sync(0xffffffffu, sB, 2);
            lA[m] = lA[m] * cA + sA; lB[m] = lB[m] * cB + sB;
            mA[m] = mAn; mB[m] = mBn;
            #pragma unroll
            for (int nt = 0; nt < 8; nt++) {
                o[m][nt][0] *= cA; o[m][nt][1] *= cA;
                o[m][nt][2] *= cB; o[m][nt][3] *= cB;
            }
        }

        // ---- O += P V : each V-frag pair feeds both m-tiles ----
        #pragma unroll
        for (int kj = 0; kj < 4; kj++) {
            unsigned pa0[4], pa1[4];
            pa0[0] = pack_bf16(s[0][2 * kj][0],     s[0][2 * kj][1]);
            pa0[1] = pack_bf16(s[0][2 * kj][2],     s[0][2 * kj][3]);
            pa0[2] = pack_bf16(s[0][2 * kj + 1][0], s[0][2 * kj + 1][1]);
            pa0[3] = pack_bf16(s[0][2 * kj + 1][2], s[0][2 * kj + 1][3]);
            pa1[0] = pack_bf16(s[1][2 * kj][0],     s[1][2 * kj][1]);
            pa1[1] = pack_bf16(s[1][2 * kj][2],     s[1][2 * kj][3]);
            pa1[2] = pack_bf16(s[1][2 * kj + 1][0], s[1][2 * kj + 1][1]);
            pa1[3] = pack_bf16(s[1][2 * kj + 1][2], s[1][2 * kj + 1][3]);
            #pragma unroll
            for (int nt = 0; nt < 8; nt++) {
                int vr = (nt * 8 + qr) * VSP + kj * 8;
                unsigned b0 = vs[vr + qc];
                unsigned b1 = vs[vr + qc + 4];
                mma_bf16(o[0][nt], pa0, b0, b1);
                mma_bf16(o[1][nt], pa1, b0, b1);
            }
        }

        // ---- pipeline: store prefetched tile i+1, sync, prefetch tile i+2 ----
        if (i < 63) {
            unsigned* ksn = sbuf + (cur ^ 1) * KVBUF;
            kv_sts(L, ksn, ksn + 32 * KSP, t);
        }
        __syncthreads();
        if (i < 62) kv_ldg(L, kp, vp, (i + 2) * 64, t);
        cur ^= 1;
    }

    // ---- normalize, stage O as [d][i] in 2 halves (stride 132), store ----
    float rA[2], rB[2];
    #pragma unroll
    for (int m = 0; m < 2; m++) { rA[m] = 1.f / lA[m]; rB[m] = 1.f / lB[m]; }
    #pragma unroll
    for (int h = 0; h < 2; h++) {
        if (h) __syncthreads();
        #pragma unroll
        for (int m = 0; m < 2; m++) {
            int rb0 = w32 + 16 * m;
            #pragma unroll
            for (int ntl = 0; ntl < 4; ntl++) {
                int nt = 4 * h + ntl;
                int rl = ntl * 8;
                ost[(rl + 2 * qc) * 132 + rb0 + qr]         = o[m][nt][0] * rA[m];
                ost[(rl + 2 * qc + 1) * 132 + rb0 + qr]     = o[m][nt][1] * rA[m];
                ost[(rl + 2 * qc) * 132 + rb0 + qr + 8]     = o[m][nt][2] * rB[m];
                ost[(rl + 2 * qc + 1) * 132 + rb0 + qr + 8] = o[m][nt][3] * rB[m];
            }
        }
        __syncthreads();
        #pragma unroll
        for (int it = 0; it < 8; it++) {
            int idx = t + it * 128;
            int dl = idx >> 5, i8 = idx & 31;
            *(float4*)&op[(size_t)(dl + 32 * h) * SS + i0 + i8 * 4] =
                *(float4*)&ost[dl * 132 + i8 * 4];
        }
    }
}

// ---------------- launch ----------------
extern "C" void kernel_launch(void* const* d_in, const int* in_sizes, int n_in,
                              void* d_out, int out_size) {
    const float* x    = (const float*)d_in[0];
    const float* gn_w = (const float*)d_in[1];
    const float* gn_b = (const float*)d_in[2];
    const float* wq   = (const float*)d_in[3];
    const float* wk   = (const float*)d_in[4];
    const float* wv   = (const float*)d_in[5];
    const float* wo   = (const float*)d_in[6];
    const float* bo   = (const float*)d_in[7];
    float* out = (float*)d_out;

    // 1) GroupNorm
    gn_kernel<<<BB * NGROUPS, 256>>>(x, gn_w, gn_b);
    // 2) Q/K/V projections (tf32 tensor core, cp.async pipeline, bf16 out)
    {
        dim3 grid(SS / 64, CC / 128, BB * 3);
        qkv_mm_kernel<<<grid, 256>>>(wq, wk, wv);
    }
    // 3) flash attention (bf16 tensor core, double-buffered K/V pipeline)
    {
        dim3 grid(SS / 128, NHH, BB);
        flash_bf16_kernel<<<grid, 128, FLASH_SMEM_BYTES>>>();
    }
    // 4) output projection + bias + residual (tf32 tensor core, cp.async)
    {
        dim3 grid(SS / 64, CC / 128, BB);
        proj_mm_kernel<<<grid, 256>>>(wo, bo, x, out);
    }
}